// round 10
// baseline (speedup 1.0000x reference)
#include <cuda_runtime.h>
#include <cuda_fp16.h>
#include <math.h>
#include <stdint.h>

// Problem constants: B=2, S=2048, E=1024, H=16, HD=64
#define B_  2
#define S_  2048
#define E_  1024
#define H_  16
#define HD_ 64
#define M_  (B_*S_)     // 4096 tokens
#define FF_ (4*E_)      // 4096

// ---------------- scratch (static device globals) --------------------------
__device__ __half h_x   [M_ * E_];
__device__ __half h_wqkv[E_ * 3 * E_];
__device__ __half h_wout[E_ * E_];
__device__ __half h_wff1[E_ * FF_];
__device__ __half h_wff2[FF_ * E_];
__device__ __half h_qkv [M_ * 3 * E_];
__device__ __half h_attn[M_ * E_];
__device__ __half h_x1  [M_ * E_];
__device__ __half h_ff1 [M_ * FF_];
__device__ float  s_proj[M_ * E_];
__device__ float  s_x1f [M_ * E_];
__device__ float  s_ff2 [M_ * E_];

__device__ __forceinline__ float gelu_f(float v) {
    return 0.5f * v * (1.0f + erff(v * 0.70710678118654752f));
}
__device__ __forceinline__ uint32_t smem_u32(const void* p) {
    uint32_t a;
    asm("{ .reg .u64 t; cvta.to.shared.u64 t, %1; cvt.u32.u64 %0, t; }"
        : "=r"(a) : "l"(p));
    return a;
}
__device__ __forceinline__ void cpa16(uint32_t s, const void* g) {
    asm volatile("cp.async.cg.shared.global [%0], [%1], 16;" :: "r"(s), "l"(g) : "memory");
}
#define CP_COMMIT() asm volatile("cp.async.commit_group;" ::: "memory")
#define CP_WAIT0()  asm volatile("cp.async.wait_group 0;" ::: "memory")
#define CP_WAIT1()  asm volatile("cp.async.wait_group 1;" ::: "memory")

__device__ __forceinline__ void ldsm4(uint32_t& r0, uint32_t& r1, uint32_t& r2,
                                      uint32_t& r3, uint32_t addr) {
    asm volatile("ldmatrix.sync.aligned.m8n8.x4.shared.b16 {%0,%1,%2,%3}, [%4];"
                 : "=r"(r0), "=r"(r1), "=r"(r2), "=r"(r3) : "r"(addr));
}
__device__ __forceinline__ void ldsm4t(uint32_t& r0, uint32_t& r1, uint32_t& r2,
                                       uint32_t& r3, uint32_t addr) {
    asm volatile("ldmatrix.sync.aligned.m8n8.x4.trans.shared.b16 {%0,%1,%2,%3}, [%4];"
                 : "=r"(r0), "=r"(r1), "=r"(r2), "=r"(r3) : "r"(addr));
}
__device__ __forceinline__ void mma_f16(float* d, const uint32_t* a, const uint32_t* b) {
    asm volatile(
        "mma.sync.aligned.m16n8k16.row.col.f32.f16.f16.f32 "
        "{%0,%1,%2,%3}, {%4,%5,%6,%7}, {%8,%9}, {%0,%1,%2,%3};"
        : "+f"(d[0]), "+f"(d[1]), "+f"(d[2]), "+f"(d[3])
        : "r"(a[0]), "r"(a[1]), "r"(a[2]), "r"(a[3]), "r"(b[0]), "r"(b[1]));
}

// ---------------------------------------------------------------------------
// fp32 -> fp16 conversion, all 5 tensors in one launch
// ---------------------------------------------------------------------------
#define CN0 (M_*E_/4)
#define CN1 (E_*3*E_/4)
#define CN2 (E_*E_/4)
#define CN3 (E_*FF_/4)
#define CN4 (FF_*E_/4)
#define CNT (CN0+CN1+CN2+CN3+CN4)

__global__ void conv_all(
    const float4* __restrict__ x,   const float4* __restrict__ wqkv,
    const float4* __restrict__ wo,  const float4* __restrict__ wf1,
    const float4* __restrict__ wf2,
    __half2* dx, __half2* dqkv, __half2* dwo, __half2* df1, __half2* df2)
{
    int j = blockIdx.x * blockDim.x + threadIdx.x;
    const float4* s; __half2* d;
    if (j < CN0)              { s = x;    d = dx;   }
    else if ((j -= CN0) < CN1){ s = wqkv; d = dqkv; }
    else if ((j -= CN1) < CN2){ s = wo;   d = dwo;  }
    else if ((j -= CN2) < CN3){ s = wf1;  d = df1;  }
    else { j -= CN3;            s = wf2;  d = df2;  }
    float4 v = s[j];
    d[2*j]   = __floats2half2_rn(v.x, v.y);
    d[2*j+1] = __floats2half2_rn(v.z, v.w);
}

// ===========================================================================
// FP16 mma.sync GEMM: C[M,N] = A[M,K] @ B[K,N] + bias (+GELU).
// CTA 128x256, BK=32, 3-stage cp.async. Warp tile 64x64 (2x4 warps).
// A stage: 128 rows x 80B stride (10240B). B: 32 rows x 528B stride (16896B).
// ===========================================================================
#define GA2 (128 * 80)
#define GB2 (32 * 528)
#define GST (GA2 + GB2)          // 27136
#define GEMM_SMEM (3 * GST)      // 81408

template<int ACT, int OUTH>
__global__ void __launch_bounds__(256, 1) gemm_h(
    const __half* __restrict__ A, const __half* __restrict__ Bm,
    const float* __restrict__ bias, void* __restrict__ Cv,
    int M, int N, int K)
{
    extern __shared__ char smraw[];
    const uint32_t sbase = smem_u32(smraw);
    const int tid = threadIdx.x, lane = tid & 31, wid = tid >> 5;
    const int wm = wid & 1, wn = wid >> 1;
    const int bm = blockIdx.y << 7, bn = blockIdx.x << 8;

    float acc[4][8][4];
    #pragma unroll
    for (int i = 0; i < 4; i++)
        #pragma unroll
        for (int j = 0; j < 8; j++)
            #pragma unroll
            for (int q = 0; q < 4; q++) acc[i][j][q] = 0.f;

    const __half* Abase = A + (size_t)bm * K;
    const __half* Bbase = Bm + bn;

    auto load_stage = [&](int kt, int slot) {
        const uint32_t a0 = sbase + (uint32_t)slot * GST;
        const uint32_t b0 = a0 + GA2;
        #pragma unroll
        for (int i = 0; i < 2; i++) {
            int idx = tid + (i << 8);
            int r = idx >> 2, c = idx & 3;
            cpa16(a0 + (uint32_t)(r * 80 + c * 16),
                  Abase + (size_t)r * K + kt * 32 + c * 8);
        }
        #pragma unroll
        for (int i = 0; i < 4; i++) {
            int idx = tid + (i << 8);
            int r = idx >> 5, c = idx & 31;
            cpa16(b0 + (uint32_t)(r * 528 + c * 16),
                  Bbase + (size_t)(kt * 32 + r) * N + c * 8);
        }
    };

    const uint32_t a_lane = (uint32_t)((lane & 15) * 80 + (lane >> 4) * 16);
    const int bK = ((lane >> 3) & 1) * 8 + (lane & 7);
    const int bN = ((lane >> 4) & 1) * 8;

    const int T = K >> 5;
    load_stage(0, 0); CP_COMMIT();
    load_stage(1, 1); CP_COMMIT();

    for (int t = 0; t < T; ++t) {
        CP_WAIT1();          // stage t complete (stage t+1 may be in flight)
        __syncthreads();     // visible to all; slot (t+2)%3 no longer read
        if (t + 2 < T) { load_stage(t + 2, (t + 2) % 3); }
        CP_COMMIT();

        const int slot = t % 3;
        const uint32_t aS = sbase + (uint32_t)slot * GST + (uint32_t)(wm * 64 * 80) + a_lane;
        const uint32_t bS = sbase + (uint32_t)slot * GST + GA2;

        #pragma unroll
        for (int kk = 0; kk < 2; kk++) {
            uint32_t af[4][4];
            #pragma unroll
            for (int mt = 0; mt < 4; mt++)
                ldsm4(af[mt][0], af[mt][1], af[mt][2], af[mt][3],
                      aS + (uint32_t)(mt * 16 * 80 + kk * 32));
            uint32_t bf[8][2];
            #pragma unroll
            for (int ntp = 0; ntp < 4; ntp++) {
                uint32_t r0, r1, r2, r3;
                uint32_t baddr = bS + (uint32_t)((kk * 16 + bK) * 528
                                + (wn * 64 + ntp * 16 + bN) * 2);
                ldsm4t(r0, r1, r2, r3, baddr);
                bf[2*ntp][0] = r0; bf[2*ntp][1] = r1;
                bf[2*ntp+1][0] = r2; bf[2*ntp+1][1] = r3;
            }
            #pragma unroll
            for (int mt = 0; mt < 4; mt++)
                #pragma unroll
                for (int nt = 0; nt < 8; nt++)
                    mma_f16(acc[mt][nt], af[mt], bf[nt]);
        }
    }

    // epilogue: bias (+gelu), fp16 or fp32 out
    #pragma unroll
    for (int mt = 0; mt < 4; mt++) {
        #pragma unroll
        for (int half = 0; half < 2; half++) {
            const int r = bm + wm * 64 + mt * 16 + (lane >> 2) + half * 8;
            #pragma unroll
            for (int nt = 0; nt < 8; nt++) {
                const int c = bn + wn * 64 + nt * 8 + (lane & 3) * 2;
                float v0 = acc[mt][nt][half * 2 + 0] + bias[c];
                float v1 = acc[mt][nt][half * 2 + 1] + bias[c + 1];
                if (ACT) { v0 = gelu_f(v0); v1 = gelu_f(v1); }
                if (OUTH) {
                    __half* C = (__half*)Cv;
                    *(__half2*)(C + (size_t)r * N + c) = __floats2half2_rn(v0, v1);
                } else {
                    float* C = (float*)Cv;
                    *(float2*)(C + (size_t)r * N + c) = make_float2(v0, v1);
                }
            }
        }
    }
}

// ===========================================================================
// Flash attention, fp16 mma. CTA: one (b,h), 64 Q rows, 8 warps 2(M)x4(N).
// Q fragments hoisted out of the KV loop (loop-invariant).
// ===========================================================================
#define OFF_Q  0
#define OFF_K  9216
#define OFF_V  (9216 + 18432)
#define OFF_SF (9216 + 18432 + 18432)
#define OFF_PH (OFF_SF + 17408)
#define OFF_RW (OFF_PH + 9216)
#define FLASH_SMEM (OFF_RW + 768)

__global__ void __launch_bounds__(256, 2) flash_h(
    const __half* __restrict__ qkv, __half* __restrict__ attn)
{
    extern __shared__ char smraw[];
    const uint32_t base = smem_u32(smraw);
    const uint32_t QsU = base + OFF_Q, KsU = base + OFF_K, VsU = base + OFF_V;
    __half* Ph  = (__half*)(smraw + OFF_PH);
    float* Sf   = (float*)(smraw + OFF_SF);
    float* mrow = (float*)(smraw + OFF_RW);
    float* lrow = mrow + 64;
    float* arow = lrow + 64;
    const uint32_t PhU = base + OFF_PH;

    const int tid = threadIdx.x, lane = tid & 31, wid = tid >> 5;
    const int wm = wid & 1, wn = wid >> 1;
    const int q0 = blockIdx.x << 6;
    const int b  = blockIdx.y >> 4, h = blockIdx.y & 15;

    const __half* qb = qkv + (size_t)b * S_ * (3 * E_) + h * HD_;
    const __half* kb = qb + E_;
    const __half* vb = qb + 2 * E_;

    // Q tile + first K/V stage (one commit group)
    #pragma unroll
    for (int i = 0; i < 2; i++) {
        int idx = tid + (i << 8);
        int r = idx >> 3, c = idx & 7;
        cpa16(QsU + (uint32_t)(r * 144 + c * 16), qb + (size_t)(q0 + r) * (3 * E_) + c * 8);
    }
    auto load_kv = [&](int t, int s) {
        #pragma unroll
        for (int i = 0; i < 2; i++) {
            int idx = tid + (i << 8);
            int r = idx >> 3, c = idx & 7;
            size_t go = (size_t)(t * 64 + r) * (3 * E_) + c * 8;
            cpa16(KsU + (uint32_t)(s * 9216 + r * 144 + c * 16), kb + go);
            cpa16(VsU + (uint32_t)(s * 9216 + r * 144 + c * 16), vb + go);
        }
    };
    load_kv(0, 0);
    CP_COMMIT();
    if (tid < 64) { mrow[tid] = -1e30f; lrow[tid] = 0.f; }

    const uint32_t a_lane = (uint32_t)((lane & 15) * 144 + (lane >> 4) * 16);
    const int rh = lane >> 2, c2 = (lane & 3) * 2;
    const int kKey = ((lane >> 4) & 1) * 8 + (lane & 7);
    const int kDb  = ((lane >> 3) & 1) * 16;
    const int vKey = ((lane >> 3) & 1) * 8 + (lane & 7);
    const int vD   = ((lane >> 4) & 1) * 8;

    CP_WAIT0();
    __syncthreads();          // Q + KV0 ready, mrow/lrow initialized

    // hoist Q fragments (loop-invariant)
    uint32_t qf[4][2][4];
    #pragma unroll
    for (int kk = 0; kk < 4; kk++)
        #pragma unroll
        for (int mt = 0; mt < 2; mt++)
            ldsm4(qf[kk][mt][0], qf[kk][mt][1], qf[kk][mt][2], qf[kk][mt][3],
                  QsU + (uint32_t)((wm * 32 + mt * 16) * 144 + kk * 32) + a_lane);

    float O[2][2][4];
    #pragma unroll
    for (int a = 0; a < 2; a++)
        #pragma unroll
        for (int bb = 0; bb < 2; bb++)
            #pragma unroll
            for (int q = 0; q < 4; q++) O[a][bb][q] = 0.f;

    const int T = S_ / 64;
    for (int t = 0; t < T; ++t) {
        const int s = t & 1;
        if (t + 1 < T) { load_kv(t + 1, s ^ 1); CP_COMMIT(); }

        // ---- S = Q K^T ----
        float sf[2][2][4];
        #pragma unroll
        for (int a = 0; a < 2; a++)
            #pragma unroll
            for (int bb = 0; bb < 2; bb++)
                #pragma unroll
                for (int q = 0; q < 4; q++) sf[a][bb][q] = 0.f;

        #pragma unroll
        for (int kk = 0; kk < 4; kk++) {
            uint32_t r0, r1, r2, r3;
            uint32_t kaddr = KsU + (uint32_t)(s * 9216 + (wn * 16 + kKey) * 144
                             + kk * 32 + kDb);
            ldsm4(r0, r1, r2, r3, kaddr);
            uint32_t bf[2][2] = {{r0, r1}, {r2, r3}};
            #pragma unroll
            for (int mt = 0; mt < 2; mt++)
                #pragma unroll
                for (int nt = 0; nt < 2; nt++)
                    mma_f16(sf[mt][nt], qf[kk][mt], bf[nt]);
        }
        // scaled S -> Sf (fp32)
        #pragma unroll
        for (int mt = 0; mt < 2; mt++)
            #pragma unroll
            for (int nt = 0; nt < 2; nt++) {
                int row0 = wm * 32 + mt * 16 + rh;
                int col  = wn * 16 + nt * 8 + c2;
                *(float2*)&Sf[row0 * 68 + col] =
                    make_float2(sf[mt][nt][0] * 0.125f, sf[mt][nt][1] * 0.125f);
                *(float2*)&Sf[(row0 + 8) * 68 + col] =
                    make_float2(sf[mt][nt][2] * 0.125f, sf[mt][nt][3] * 0.125f);
            }
        __syncthreads();

        // ---- online softmax: 4 threads/row; write P fp16 ----
        {
            int row = tid >> 2;
            float* sr = Sf + row * 68 + (tid & 3) * 16;
            float4 v0 = *(float4*)(sr),     v1 = *(float4*)(sr + 4),
                   v2 = *(float4*)(sr + 8), v3 = *(float4*)(sr + 12);
            float mx = fmaxf(fmaxf(fmaxf(v0.x, v0.y), fmaxf(v0.z, v0.w)),
                             fmaxf(fmaxf(v1.x, v1.y), fmaxf(v1.z, v1.w)));
            mx = fmaxf(mx, fmaxf(fmaxf(fmaxf(v2.x, v2.y), fmaxf(v2.z, v2.w)),
                                 fmaxf(fmaxf(v3.x, v3.y), fmaxf(v3.z, v3.w))));
            mx = fmaxf(mx, __shfl_xor_sync(0xffffffffu, mx, 1));
            mx = fmaxf(mx, __shfl_xor_sync(0xffffffffu, mx, 2));
            float mo = mrow[row];
            float mn = fmaxf(mo, mx);
            v0.x = __expf(v0.x - mn); v0.y = __expf(v0.y - mn);
            v0.z = __expf(v0.z - mn); v0.w = __expf(v0.w - mn);
            v1.x = __expf(v1.x - mn); v1.y = __expf(v1.y - mn);
            v1.z = __expf(v1.z - mn); v1.w = __expf(v1.w - mn);
            v2.x = __expf(v2.x - mn); v2.y = __expf(v2.y - mn);
            v2.z = __expf(v2.z - mn); v2.w = __expf(v2.w - mn);
            v3.x = __expf(v3.x - mn); v3.y = __expf(v3.y - mn);
            v3.z = __expf(v3.z - mn); v3.w = __expf(v3.w - mn);
            __half2 hp[8];
            hp[0] = __floats2half2_rn(v0.x, v0.y); hp[1] = __floats2half2_rn(v0.z, v0.w);
            hp[2] = __floats2half2_rn(v1.x, v1.y); hp[3] = __floats2half2_rn(v1.z, v1.w);
            hp[4] = __floats2half2_rn(v2.x, v2.y); hp[5] = __floats2half2_rn(v2.z, v2.w);
            hp[6] = __floats2half2_rn(v3.x, v3.y); hp[7] = __floats2half2_rn(v3.z, v3.w);
            uint4* pdst = (uint4*)(Ph + row * 72 + (tid & 3) * 16);
            pdst[0] = *(uint4*)&hp[0];
            pdst[1] = *(uint4*)&hp[4];
            float su = v0.x + v0.y + v0.z + v0.w + v1.x + v1.y + v1.z + v1.w
                     + v2.x + v2.y + v2.z + v2.w + v3.x + v3.y + v3.z + v3.w;
            su += __shfl_xor_sync(0xffffffffu, su, 1);
            su += __shfl_xor_sync(0xffffffffu, su, 2);
            if ((tid & 3) == 0) {
                float al = __expf(mo - mn);
                arow[row] = al;
                lrow[row] = lrow[row] * al + su;
                mrow[row] = mn;
            }
        }
        __syncthreads();

        // ---- rescale O; O += P @ V ----
        #pragma unroll
        for (int mt = 0; mt < 2; mt++) {
            float a0 = arow[wm * 32 + mt * 16 + rh];
            float a1 = arow[wm * 32 + mt * 16 + 8 + rh];
            #pragma unroll
            for (int nt = 0; nt < 2; nt++) {
                O[mt][nt][0] *= a0; O[mt][nt][1] *= a0;
                O[mt][nt][2] *= a1; O[mt][nt][3] *= a1;
            }
        }
        #pragma unroll
        for (int kk = 0; kk < 4; kk++) {
            uint32_t af[2][4];
            #pragma unroll
            for (int mt = 0; mt < 2; mt++)
                ldsm4(af[mt][0], af[mt][1], af[mt][2], af[mt][3],
                      PhU + (uint32_t)((wm * 32 + mt * 16) * 144 + kk * 32) + a_lane);
            uint32_t r0, r1, r2, r3;
            uint32_t vaddr = VsU + (uint32_t)(s * 9216 + (kk * 16 + vKey) * 144
                             + (wn * 16 + vD) * 2);
            ldsm4t(r0, r1, r2, r3, vaddr);
            uint32_t bf[2][2] = {{r0, r1}, {r2, r3}};
            #pragma unroll
            for (int mt = 0; mt < 2; mt++)
                #pragma unroll
                for (int nt = 0; nt < 2; nt++)
                    mma_f16(O[mt][nt], af[mt], bf[nt]);
        }

        // KV t+1 ready + all warps done with slot s and Ph before next iter
        if (t + 1 < T) CP_WAIT0();
        __syncthreads();
    }

    // ---- normalize + write fp16 ----
    #pragma unroll
    for (int mt = 0; mt < 2; mt++) {
        int row0 = wm * 32 + mt * 16 + rh;
        float inv0 = 1.f / lrow[row0];
        float inv1 = 1.f / lrow[row0 + 8];
        #pragma unroll
        for (int nt = 0; nt < 2; nt++) {
            int col = h * HD_ + wn * 16 + nt * 8 + c2;
            *(__half2*)&attn[(size_t)(b * S_ + q0 + row0) * E_ + col] =
                __floats2half2_rn(O[mt][nt][0] * inv0, O[mt][nt][1] * inv0);
            *(__half2*)&attn[(size_t)(b * S_ + q0 + row0 + 8) * E_ + col] =
                __floats2half2_rn(O[mt][nt][2] * inv1, O[mt][nt][3] * inv1);
        }
    }
}

// ---------------------------------------------------------------------------
// Fused residual-add + LayerNorm; optional fp16 secondary output.
// ---------------------------------------------------------------------------
template<int WH>
__global__ void __launch_bounds__(256) ln_kernel(
    const float* __restrict__ a, const float* __restrict__ bsrc,
    const float* __restrict__ g, const float* __restrict__ be,
    float* __restrict__ out, __half* __restrict__ outh)
{
    const int tok = blockIdx.x;
    const int tid = threadIdx.x;
    const float* pa = a    + (size_t)tok * E_;
    const float* pb = bsrc + (size_t)tok * E_;

    float r[4]; float s = 0.f;
    #pragma unroll
    for (int i = 0; i < 4; i++) {
        int e = tid + (i << 8);
        r[i] = pa[e] + pb[e];
        s += r[i];
    }
    __shared__ float red[8];
    #pragma unroll
    for (int o = 16; o > 0; o >>= 1) s += __shfl_xor_sync(0xffffffffu, s, o);
    if ((tid & 31) == 0) red[tid >> 5] = s;
    __syncthreads();
    float tot = 0.f;
    #pragma unroll
    for (int w = 0; w < 8; w++) tot += red[w];
    const float mean = tot * (1.0f / E_);

    float vs = 0.f;
    #pragma unroll
    for (int i = 0; i < 4; i++) { float d = r[i] - mean; vs += d * d; }
    #pragma unroll
    for (int o = 16; o > 0; o >>= 1) vs += __shfl_xor_sync(0xffffffffu, vs, o);
    __syncthreads();
    if ((tid & 31) == 0) red[tid >> 5] = vs;
    __syncthreads();
    float vtot = 0.f;
    #pragma unroll
    for (int w = 0; w < 8; w++) vtot += red[w];
    const float rstd = rsqrtf(vtot * (1.0f / E_) + 1e-5f);

    #pragma unroll
    for (int i = 0; i < 4; i++) {
        int e = tid + (i << 8);
        float v = (r[i] - mean) * rstd * g[e] + be[e];
        out[(size_t)tok * E_ + e] = v;
        if (WH) outh[(size_t)tok * E_ + e] = __float2half(v);
    }
}

// ---------------------------------------------------------------------------
extern "C" void kernel_launch(void* const* d_in, const int* in_sizes, int n_in,
                              void* d_out, int out_size)
{
    const float* x     = (const float*)d_in[0];
    const float* w_qkv = (const float*)d_in[1];
    const float* b_qkv = (const float*)d_in[2];
    const float* w_out = (const float*)d_in[3];
    const float* b_out = (const float*)d_in[4];
    const float* w_ff1 = (const float*)d_in[5];
    const float* b_ff1 = (const float*)d_in[6];
    const float* w_ff2 = (const float*)d_in[7];
    const float* b_ff2 = (const float*)d_in[8];
    const float* g1    = (const float*)d_in[9];
    const float* be1   = (const float*)d_in[10];
    const float* g2    = (const float*)d_in[11];
    const float* be2   = (const float*)d_in[12];
    float* out = (float*)d_out;

    __half *p_hx, *p_wqkv, *p_wout, *p_wff1, *p_wff2;
    __half *p_qkv, *p_attn, *p_x1h, *p_ff1;
    float *p_proj, *p_x1f, *p_ff2;
    cudaGetSymbolAddress((void**)&p_hx,   h_x);
    cudaGetSymbolAddress((void**)&p_wqkv, h_wqkv);
    cudaGetSymbolAddress((void**)&p_wout, h_wout);
    cudaGetSymbolAddress((void**)&p_wff1, h_wff1);
    cudaGetSymbolAddress((void**)&p_wff2, h_wff2);
    cudaGetSymbolAddress((void**)&p_qkv,  h_qkv);
    cudaGetSymbolAddress((void**)&p_attn, h_attn);
    cudaGetSymbolAddress((void**)&p_x1h,  h_x1);
    cudaGetSymbolAddress((void**)&p_ff1,  h_ff1);
    cudaGetSymbolAddress((void**)&p_proj, s_proj);
    cudaGetSymbolAddress((void**)&p_x1f,  s_x1f);
    cudaGetSymbolAddress((void**)&p_ff2,  s_ff2);

    cudaFuncSetAttribute(gemm_h<0,1>, cudaFuncAttributeMaxDynamicSharedMemorySize, GEMM_SMEM);
    cudaFuncSetAttribute(gemm_h<0,0>, cudaFuncAttributeMaxDynamicSharedMemorySize, GEMM_SMEM);
    cudaFuncSetAttribute(gemm_h<1,1>, cudaFuncAttributeMaxDynamicSharedMemorySize, GEMM_SMEM);
    cudaFuncSetAttribute(flash_h,     cudaFuncAttributeMaxDynamicSharedMemorySize, FLASH_SMEM);

    // 0) fp32 -> fp16 conversions (single launch)
    conv_all<<<CNT / 256, 256>>>(
        (const float4*)x, (const float4*)w_qkv, (const float4*)w_out,
        (const float4*)w_ff1, (const float4*)w_ff2,
        (__half2*)p_hx, (__half2*)p_wqkv, (__half2*)p_wout,
        (__half2*)p_wff1, (__half2*)p_wff2);

    // 1) QKV projection (fp16 out)
    gemm_h<0,1><<<dim3(3 * E_ / 256, M_ / 128), 256, GEMM_SMEM>>>(
        p_hx, p_wqkv, b_qkv, p_qkv, M_, 3 * E_, E_);

    // 2) flash attention (fp16)
    flash_h<<<dim3(S_ / 64, B_ * H_), 256, FLASH_SMEM>>>(p_qkv, p_attn);

    // 3) output projection (fp32 out)
    gemm_h<0,0><<<dim3(E_ / 256, M_ / 128), 256, GEMM_SMEM>>>(
        p_attn, p_wout, b_out, p_proj, M_, E_, E_);

    // 4) LN1 (fp32 + fp16 out)
    ln_kernel<1><<<M_, 256>>>(x, p_proj, g1, be1, p_x1f, p_x1h);

    // 5) FF1 + GELU (fp16 out)
    gemm_h<1,1><<<dim3(FF_ / 256, M_ / 128), 256, GEMM_SMEM>>>(
        p_x1h, p_wff1, b_ff1, p_ff1, M_, FF_, E_);

    // 6) FF2 (fp32 out)
    gemm_h<0,0><<<dim3(E_ / 256, M_ / 128), 256, GEMM_SMEM>>>(
        p_ff1, p_wff2, b_ff2, p_ff2, M_, E_, FF_);

    // 7) LN2 -> output
    ln_kernel<0><<<M_, 256>>>(p_x1f, p_ff2, g2, be2, out, nullptr);
}

// round 12
// speedup vs baseline: 1.0810x; 1.0810x over previous
#include <cuda_runtime.h>
#include <cuda_fp16.h>
#include <math.h>
#include <stdint.h>

// Problem constants: B=2, S=2048, E=1024, H=16, HD=64
#define B_  2
#define S_  2048
#define E_  1024
#define H_  16
#define HD_ 64
#define M_  (B_*S_)     // 4096 tokens
#define FF_ (4*E_)      // 4096

// ---------------- scratch (static device globals) --------------------------
__device__ __half h_x   [M_ * E_];
__device__ __half h_wqkv[E_ * 3 * E_];
__device__ __half h_wout[E_ * E_];
__device__ __half h_wff1[E_ * FF_];
__device__ __half h_wff2[FF_ * E_];
__device__ __half h_qkv [M_ * 3 * E_];
__device__ __half h_attn[M_ * E_];
__device__ __half h_x1  [M_ * E_];
__device__ __half h_ff1 [M_ * FF_];
__device__ float  s_proj[M_ * E_];
__device__ float  s_x1f [M_ * E_];
__device__ float  s_ff2 [M_ * E_];

__device__ __forceinline__ float gelu_f(float v) {
    return 0.5f * v * (1.0f + erff(v * 0.70710678118654752f));
}
__device__ __forceinline__ uint32_t smem_u32(const void* p) {
    uint32_t a;
    asm("{ .reg .u64 t; cvta.to.shared.u64 t, %1; cvt.u32.u64 %0, t; }"
        : "=r"(a) : "l"(p));
    return a;
}
__device__ __forceinline__ void cpa16(uint32_t s, const void* g) {
    asm volatile("cp.async.cg.shared.global [%0], [%1], 16;" :: "r"(s), "l"(g) : "memory");
}
#define CP_COMMIT() asm volatile("cp.async.commit_group;" ::: "memory")
#define CP_WAIT0()  asm volatile("cp.async.wait_group 0;" ::: "memory")
#define CP_WAIT1()  asm volatile("cp.async.wait_group 1;" ::: "memory")

__device__ __forceinline__ void ldsm4(uint32_t& r0, uint32_t& r1, uint32_t& r2,
                                      uint32_t& r3, uint32_t addr) {
    asm volatile("ldmatrix.sync.aligned.m8n8.x4.shared.b16 {%0,%1,%2,%3}, [%4];"
                 : "=r"(r0), "=r"(r1), "=r"(r2), "=r"(r3) : "r"(addr));
}
__device__ __forceinline__ void ldsm4t(uint32_t& r0, uint32_t& r1, uint32_t& r2,
                                       uint32_t& r3, uint32_t addr) {
    asm volatile("ldmatrix.sync.aligned.m8n8.x4.trans.shared.b16 {%0,%1,%2,%3}, [%4];"
                 : "=r"(r0), "=r"(r1), "=r"(r2), "=r"(r3) : "r"(addr));
}
__device__ __forceinline__ void mma_f16(float* d, const uint32_t* a, const uint32_t* b) {
    asm volatile(
        "mma.sync.aligned.m16n8k16.row.col.f32.f16.f16.f32 "
        "{%0,%1,%2,%3}, {%4,%5,%6,%7}, {%8,%9}, {%0,%1,%2,%3};"
        : "+f"(d[0]), "+f"(d[1]), "+f"(d[2]), "+f"(d[3])
        : "r"(a[0]), "r"(a[1]), "r"(a[2]), "r"(a[3]), "r"(b[0]), "r"(b[1]));
}

// ---------------------------------------------------------------------------
// fp32 -> fp16 conversion, all 5 tensors in one launch
// ---------------------------------------------------------------------------
#define CN0 (M_*E_/4)
#define CN1 (E_*3*E_/4)
#define CN2 (E_*E_/4)
#define CN3 (E_*FF_/4)
#define CN4 (FF_*E_/4)
#define CNT (CN0+CN1+CN2+CN3+CN4)

__global__ void conv_all(
    const float4* __restrict__ x,   const float4* __restrict__ wqkv,
    const float4* __restrict__ wo,  const float4* __restrict__ wf1,
    const float4* __restrict__ wf2,
    __half2* dx, __half2* dqkv, __half2* dwo, __half2* df1, __half2* df2)
{
    int j = blockIdx.x * blockDim.x + threadIdx.x;
    const float4* s; __half2* d;
    if (j < CN0)              { s = x;    d = dx;   }
    else if ((j -= CN0) < CN1){ s = wqkv; d = dqkv; }
    else if ((j -= CN1) < CN2){ s = wo;   d = dwo;  }
    else if ((j -= CN2) < CN3){ s = wf1;  d = df1;  }
    else { j -= CN3;            s = wf2;  d = df2;  }
    float4 v = s[j];
    d[2*j]   = __floats2half2_rn(v.x, v.y);
    d[2*j+1] = __floats2half2_rn(v.z, v.w);
}

// ===========================================================================
// FP16 mma.sync GEMM: C[M,N] = A[M,K] @ B[K,N] + bias (+GELU).
// CTA 128x128, BK=32, 3-stage cp.async, 2 CTAs/SM. Warp tile 64x32 (2x4).
// A stage: 128 rows x 80B stride (10240B). B: 32 rows x 272B stride (8704B).
// ===========================================================================
#define GA_BYTES (128 * 80)          // 10240
#define GB_BYTES (32 * 272)          // 8704
#define GSTG (GA_BYTES + GB_BYTES)   // 18944
#define GEMM_SMEM (3 * GSTG)         // 56832

template<int ACT, int OUTH>
__global__ void __launch_bounds__(256, 2) gemm_h(
    const __half* __restrict__ A, const __half* __restrict__ Bm,
    const float* __restrict__ bias, void* __restrict__ Cv,
    int M, int N, int K)
{
    extern __shared__ char smraw[];
    const uint32_t sbase = smem_u32(smraw);
    const int tid = threadIdx.x, lane = tid & 31, wid = tid >> 5;
    const int wm = wid & 1, wn = wid >> 1;
    const int bm = blockIdx.y << 7, bn = blockIdx.x << 7;

    float acc[4][4][4];
    #pragma unroll
    for (int i = 0; i < 4; i++)
        #pragma unroll
        for (int j = 0; j < 4; j++)
            #pragma unroll
            for (int q = 0; q < 4; q++) acc[i][j][q] = 0.f;

    const __half* Abase = A + (size_t)bm * K;
    const __half* Bbase = Bm + bn;

    auto load_stage = [&](int kt, int slot) {
        const uint32_t a0 = sbase + (uint32_t)slot * GSTG;
        const uint32_t b0 = a0 + GA_BYTES;
        #pragma unroll
        for (int i = 0; i < 2; i++) {
            int idx = tid + (i << 8);
            int r = idx >> 2, c = idx & 3;
            cpa16(a0 + (uint32_t)(r * 80 + c * 16),
                  Abase + (size_t)r * K + kt * 32 + c * 8);
        }
        #pragma unroll
        for (int i = 0; i < 2; i++) {
            int idx = tid + (i << 8);
            int r = idx >> 4, c = idx & 15;
            cpa16(b0 + (uint32_t)(r * 272 + c * 16),
                  Bbase + (size_t)(kt * 32 + r) * N + c * 8);
        }
    };

    const uint32_t a_lane = (uint32_t)((lane & 15) * 80 + (lane >> 4) * 16);
    const int bK = ((lane >> 3) & 1) * 8 + (lane & 7);
    const int bN = ((lane >> 4) & 1) * 8;

    const int T = K >> 5;
    load_stage(0, 0); CP_COMMIT();
    load_stage(1, 1); CP_COMMIT();

    for (int t = 0; t < T; ++t) {
        CP_WAIT1();          // stage t complete; stage t+1 may still be in flight
        __syncthreads();     // all warps done reading slot (t+2)%3
        if (t + 2 < T) load_stage(t + 2, (t + 2) % 3);
        CP_COMMIT();         // unconditional: keeps group counting uniform

        const int slot = t % 3;
        const uint32_t aS = sbase + (uint32_t)slot * GSTG + (uint32_t)(wm * 64 * 80) + a_lane;
        const uint32_t bS = sbase + (uint32_t)slot * GSTG + GA_BYTES;

        #pragma unroll
        for (int kk = 0; kk < 2; kk++) {
            uint32_t af[4][4];
            #pragma unroll
            for (int mt = 0; mt < 4; mt++)
                ldsm4(af[mt][0], af[mt][1], af[mt][2], af[mt][3],
                      aS + (uint32_t)(mt * 16 * 80 + kk * 32));
            uint32_t bf[4][2];
            #pragma unroll
            for (int ntp = 0; ntp < 2; ntp++) {
                uint32_t r0, r1, r2, r3;
                uint32_t baddr = bS + (uint32_t)((kk * 16 + bK) * 272
                                + (wn * 32 + ntp * 16 + bN) * 2);
                ldsm4t(r0, r1, r2, r3, baddr);
                bf[2*ntp][0] = r0; bf[2*ntp][1] = r1;
                bf[2*ntp+1][0] = r2; bf[2*ntp+1][1] = r3;
            }
            #pragma unroll
            for (int mt = 0; mt < 4; mt++)
                #pragma unroll
                for (int nt = 0; nt < 4; nt++)
                    mma_f16(acc[mt][nt], af[mt], bf[nt]);
        }
    }

    // epilogue: bias (+gelu), fp16 or fp32 out
    #pragma unroll
    for (int mt = 0; mt < 4; mt++) {
        #pragma unroll
        for (int half = 0; half < 2; half++) {
            const int r = bm + wm * 64 + mt * 16 + (lane >> 2) + half * 8;
            #pragma unroll
            for (int nt = 0; nt < 4; nt++) {
                const int c = bn + wn * 32 + nt * 8 + (lane & 3) * 2;
                float v0 = acc[mt][nt][half * 2 + 0] + bias[c];
                float v1 = acc[mt][nt][half * 2 + 1] + bias[c + 1];
                if (ACT) { v0 = gelu_f(v0); v1 = gelu_f(v1); }
                if (OUTH) {
                    __half* C = (__half*)Cv;
                    *(__half2*)(C + (size_t)r * N + c) = __floats2half2_rn(v0, v1);
                } else {
                    float* C = (float*)Cv;
                    *(float2*)(C + (size_t)r * N + c) = make_float2(v0, v1);
                }
            }
        }
    }
}

// ===========================================================================
// Flash attention, fp16 mma. CTA: one (b,h), 64 Q rows, 8 warps 2(M)x4(N).
// Q fragments hoisted out of the KV loop (loop-invariant).
// ===========================================================================
#define OFF_Q  0
#define OFF_K  9216
#define OFF_V  (9216 + 18432)
#define OFF_SF (9216 + 18432 + 18432)
#define OFF_PH (OFF_SF + 17408)
#define OFF_RW (OFF_PH + 9216)
#define FLASH_SMEM (OFF_RW + 768)

__global__ void __launch_bounds__(256, 2) flash_h(
    const __half* __restrict__ qkv, __half* __restrict__ attn)
{
    extern __shared__ char smraw[];
    const uint32_t base = smem_u32(smraw);
    const uint32_t QsU = base + OFF_Q, KsU = base + OFF_K, VsU = base + OFF_V;
    __half* Ph  = (__half*)(smraw + OFF_PH);
    float* Sf   = (float*)(smraw + OFF_SF);
    float* mrow = (float*)(smraw + OFF_RW);
    float* lrow = mrow + 64;
    float* arow = lrow + 64;
    const uint32_t PhU = base + OFF_PH;

    const int tid = threadIdx.x, lane = tid & 31, wid = tid >> 5;
    const int wm = wid & 1, wn = wid >> 1;
    const int q0 = blockIdx.x << 6;
    const int b  = blockIdx.y >> 4, h = blockIdx.y & 15;

    const __half* qb = qkv + (size_t)b * S_ * (3 * E_) + h * HD_;
    const __half* kb = qb + E_;
    const __half* vb = qb + 2 * E_;

    // Q tile + first K/V stage (one commit group)
    #pragma unroll
    for (int i = 0; i < 2; i++) {
        int idx = tid + (i << 8);
        int r = idx >> 3, c = idx & 7;
        cpa16(QsU + (uint32_t)(r * 144 + c * 16), qb + (size_t)(q0 + r) * (3 * E_) + c * 8);
    }
    auto load_kv = [&](int t, int s) {
        #pragma unroll
        for (int i = 0; i < 2; i++) {
            int idx = tid + (i << 8);
            int r = idx >> 3, c = idx & 7;
            size_t go = (size_t)(t * 64 + r) * (3 * E_) + c * 8;
            cpa16(KsU + (uint32_t)(s * 9216 + r * 144 + c * 16), kb + go);
            cpa16(VsU + (uint32_t)(s * 9216 + r * 144 + c * 16), vb + go);
        }
    };
    load_kv(0, 0);
    CP_COMMIT();
    if (tid < 64) { mrow[tid] = -1e30f; lrow[tid] = 0.f; }

    const uint32_t a_lane = (uint32_t)((lane & 15) * 144 + (lane >> 4) * 16);
    const int rh = lane >> 2, c2 = (lane & 3) * 2;
    const int kKey = ((lane >> 4) & 1) * 8 + (lane & 7);
    const int kDb  = ((lane >> 3) & 1) * 16;
    const int vKey = ((lane >> 3) & 1) * 8 + (lane & 7);
    const int vD   = ((lane >> 4) & 1) * 8;

    CP_WAIT0();
    __syncthreads();          // Q + KV0 ready, mrow/lrow initialized

    // hoist Q fragments (loop-invariant)
    uint32_t qf[4][2][4];
    #pragma unroll
    for (int kk = 0; kk < 4; kk++)
        #pragma unroll
        for (int mt = 0; mt < 2; mt++)
            ldsm4(qf[kk][mt][0], qf[kk][mt][1], qf[kk][mt][2], qf[kk][mt][3],
                  QsU + (uint32_t)((wm * 32 + mt * 16) * 144 + kk * 32) + a_lane);

    float O[2][2][4];
    #pragma unroll
    for (int a = 0; a < 2; a++)
        #pragma unroll
        for (int bb = 0; bb < 2; bb++)
            #pragma unroll
            for (int q = 0; q < 4; q++) O[a][bb][q] = 0.f;

    const int T = S_ / 64;
    for (int t = 0; t < T; ++t) {
        const int s = t & 1;
        if (t + 1 < T) { load_kv(t + 1, s ^ 1); CP_COMMIT(); }

        // ---- S = Q K^T ----
        float sf[2][2][4];
        #pragma unroll
        for (int a = 0; a < 2; a++)
            #pragma unroll
            for (int bb = 0; bb < 2; bb++)
                #pragma unroll
                for (int q = 0; q < 4; q++) sf[a][bb][q] = 0.f;

        #pragma unroll
        for (int kk = 0; kk < 4; kk++) {
            uint32_t r0, r1, r2, r3;
            uint32_t kaddr = KsU + (uint32_t)(s * 9216 + (wn * 16 + kKey) * 144
                             + kk * 32 + kDb);
            ldsm4(r0, r1, r2, r3, kaddr);
            uint32_t bf[2][2] = {{r0, r1}, {r2, r3}};
            #pragma unroll
            for (int mt = 0; mt < 2; mt++)
                #pragma unroll
                for (int nt = 0; nt < 2; nt++)
                    mma_f16(sf[mt][nt], qf[kk][mt], bf[nt]);
        }
        // scaled S -> Sf (fp32)
        #pragma unroll
        for (int mt = 0; mt < 2; mt++)
            #pragma unroll
            for (int nt = 0; nt < 2; nt++) {
                int row0 = wm * 32 + mt * 16 + rh;
                int col  = wn * 16 + nt * 8 + c2;
                *(float2*)&Sf[row0 * 68 + col] =
                    make_float2(sf[mt][nt][0] * 0.125f, sf[mt][nt][1] * 0.125f);
                *(float2*)&Sf[(row0 + 8) * 68 + col] =
                    make_float2(sf[mt][nt][2] * 0.125f, sf[mt][nt][3] * 0.125f);
            }
        __syncthreads();

        // ---- online softmax: 4 threads/row; write P fp16 ----
        {
            int row = tid >> 2;
            float* sr = Sf + row * 68 + (tid & 3) * 16;
            float4 v0 = *(float4*)(sr),     v1 = *(float4*)(sr + 4),
                   v2 = *(float4*)(sr + 8), v3 = *(float4*)(sr + 12);
            float mx = fmaxf(fmaxf(fmaxf(v0.x, v0.y), fmaxf(v0.z, v0.w)),
                             fmaxf(fmaxf(v1.x, v1.y), fmaxf(v1.z, v1.w)));
            mx = fmaxf(mx, fmaxf(fmaxf(fmaxf(v2.x, v2.y), fmaxf(v2.z, v2.w)),
                                 fmaxf(fmaxf(v3.x, v3.y), fmaxf(v3.z, v3.w))));
            mx = fmaxf(mx, __shfl_xor_sync(0xffffffffu, mx, 1));
            mx = fmaxf(mx, __shfl_xor_sync(0xffffffffu, mx, 2));
            float mo = mrow[row];
            float mn = fmaxf(mo, mx);
            v0.x = __expf(v0.x - mn); v0.y = __expf(v0.y - mn);
            v0.z = __expf(v0.z - mn); v0.w = __expf(v0.w - mn);
            v1.x = __expf(v1.x - mn); v1.y = __expf(v1.y - mn);
            v1.z = __expf(v1.z - mn); v1.w = __expf(v1.w - mn);
            v2.x = __expf(v2.x - mn); v2.y = __expf(v2.y - mn);
            v2.z = __expf(v2.z - mn); v2.w = __expf(v2.w - mn);
            v3.x = __expf(v3.x - mn); v3.y = __expf(v3.y - mn);
            v3.z = __expf(v3.z - mn); v3.w = __expf(v3.w - mn);
            __half2 hp[8];
            hp[0] = __floats2half2_rn(v0.x, v0.y); hp[1] = __floats2half2_rn(v0.z, v0.w);
            hp[2] = __floats2half2_rn(v1.x, v1.y); hp[3] = __floats2half2_rn(v1.z, v1.w);
            hp[4] = __floats2half2_rn(v2.x, v2.y); hp[5] = __floats2half2_rn(v2.z, v2.w);
            hp[6] = __floats2half2_rn(v3.x, v3.y); hp[7] = __floats2half2_rn(v3.z, v3.w);
            uint4* pdst = (uint4*)(Ph + row * 72 + (tid & 3) * 16);
            pdst[0] = *(uint4*)&hp[0];
            pdst[1] = *(uint4*)&hp[4];
            float su = v0.x + v0.y + v0.z + v0.w + v1.x + v1.y + v1.z + v1.w
                     + v2.x + v2.y + v2.z + v2.w + v3.x + v3.y + v3.z + v3.w;
            su += __shfl_xor_sync(0xffffffffu, su, 1);
            su += __shfl_xor_sync(0xffffffffu, su, 2);
            if ((tid & 3) == 0) {
                float al = __expf(mo - mn);
                arow[row] = al;
                lrow[row] = lrow[row] * al + su;
                mrow[row] = mn;
            }
        }
        __syncthreads();

        // ---- rescale O; O += P @ V ----
        #pragma unroll
        for (int mt = 0; mt < 2; mt++) {
            float a0 = arow[wm * 32 + mt * 16 + rh];
            float a1 = arow[wm * 32 + mt * 16 + 8 + rh];
            #pragma unroll
            for (int nt = 0; nt < 2; nt++) {
                O[mt][nt][0] *= a0; O[mt][nt][1] *= a0;
                O[mt][nt][2] *= a1; O[mt][nt][3] *= a1;
            }
        }
        #pragma unroll
        for (int kk = 0; kk < 4; kk++) {
            uint32_t af[2][4];
            #pragma unroll
            for (int mt = 0; mt < 2; mt++)
                ldsm4(af[mt][0], af[mt][1], af[mt][2], af[mt][3],
                      PhU + (uint32_t)((wm * 32 + mt * 16) * 144 + kk * 32) + a_lane);
            uint32_t r0, r1, r2, r3;
            uint32_t vaddr = VsU + (uint32_t)(s * 9216 + (kk * 16 + vKey) * 144
                             + (wn * 16 + vD) * 2);
            ldsm4t(r0, r1, r2, r3, vaddr);
            uint32_t bf[2][2] = {{r0, r1}, {r2, r3}};
            #pragma unroll
            for (int mt = 0; mt < 2; mt++)
                #pragma unroll
                for (int nt = 0; nt < 2; nt++)
                    mma_f16(O[mt][nt], af[mt], bf[nt]);
        }

        // KV t+1 ready + all warps done with slot s and Ph before next iter
        if (t + 1 < T) CP_WAIT0();
        __syncthreads();
    }

    // ---- normalize + write fp16 ----
    #pragma unroll
    for (int mt = 0; mt < 2; mt++) {
        int row0 = wm * 32 + mt * 16 + rh;
        float inv0 = 1.f / lrow[row0];
        float inv1 = 1.f / lrow[row0 + 8];
        #pragma unroll
        for (int nt = 0; nt < 2; nt++) {
            int col = h * HD_ + wn * 16 + nt * 8 + c2;
            *(__half2*)&attn[(size_t)(b * S_ + q0 + row0) * E_ + col] =
                __floats2half2_rn(O[mt][nt][0] * inv0, O[mt][nt][1] * inv0);
            *(__half2*)&attn[(size_t)(b * S_ + q0 + row0 + 8) * E_ + col] =
                __floats2half2_rn(O[mt][nt][2] * inv1, O[mt][nt][3] * inv1);
        }
    }
}

// ---------------------------------------------------------------------------
// Fused residual-add + LayerNorm; optional fp16 secondary output.
// ---------------------------------------------------------------------------
template<int WH>
__global__ void __launch_bounds__(256) ln_kernel(
    const float* __restrict__ a, const float* __restrict__ bsrc,
    const float* __restrict__ g, const float* __restrict__ be,
    float* __restrict__ out, __half* __restrict__ outh)
{
    const int tok = blockIdx.x;
    const int tid = threadIdx.x;
    const float* pa = a    + (size_t)tok * E_;
    const float* pb = bsrc + (size_t)tok * E_;

    float r[4]; float s = 0.f;
    #pragma unroll
    for (int i = 0; i < 4; i++) {
        int e = tid + (i << 8);
        r[i] = pa[e] + pb[e];
        s += r[i];
    }
    __shared__ float red[8];
    #pragma unroll
    for (int o = 16; o > 0; o >>= 1) s += __shfl_xor_sync(0xffffffffu, s, o);
    if ((tid & 31) == 0) red[tid >> 5] = s;
    __syncthreads();
    float tot = 0.f;
    #pragma unroll
    for (int w = 0; w < 8; w++) tot += red[w];
    const float mean = tot * (1.0f / E_);

    float vs = 0.f;
    #pragma unroll
    for (int i = 0; i < 4; i++) { float d = r[i] - mean; vs += d * d; }
    #pragma unroll
    for (int o = 16; o > 0; o >>= 1) vs += __shfl_xor_sync(0xffffffffu, vs, o);
    __syncthreads();
    if ((tid & 31) == 0) red[tid >> 5] = vs;
    __syncthreads();
    float vtot = 0.f;
    #pragma unroll
    for (int w = 0; w < 8; w++) vtot += red[w];
    const float rstd = rsqrtf(vtot * (1.0f / E_) + 1e-5f);

    #pragma unroll
    for (int i = 0; i < 4; i++) {
        int e = tid + (i << 8);
        float v = (r[i] - mean) * rstd * g[e] + be[e];
        out[(size_t)tok * E_ + e] = v;
        if (WH) outh[(size_t)tok * E_ + e] = __float2half(v);
    }
}

// ---------------------------------------------------------------------------
extern "C" void kernel_launch(void* const* d_in, const int* in_sizes, int n_in,
                              void* d_out, int out_size)
{
    const float* x     = (const float*)d_in[0];
    const float* w_qkv = (const float*)d_in[1];
    const float* b_qkv = (const float*)d_in[2];
    const float* w_out = (const float*)d_in[3];
    const float* b_out = (const float*)d_in[4];
    const float* w_ff1 = (const float*)d_in[5];
    const float* b_ff1 = (const float*)d_in[6];
    const float* w_ff2 = (const float*)d_in[7];
    const float* b_ff2 = (const float*)d_in[8];
    const float* g1    = (const float*)d_in[9];
    const float* be1   = (const float*)d_in[10];
    const float* g2    = (const float*)d_in[11];
    const float* be2   = (const float*)d_in[12];
    float* out = (float*)d_out;

    __half *p_hx, *p_wqkv, *p_wout, *p_wff1, *p_wff2;
    __half *p_qkv, *p_attn, *p_x1h, *p_ff1;
    float *p_proj, *p_x1f, *p_ff2;
    cudaGetSymbolAddress((void**)&p_hx,   h_x);
    cudaGetSymbolAddress((void**)&p_wqkv, h_wqkv);
    cudaGetSymbolAddress((void**)&p_wout, h_wout);
    cudaGetSymbolAddress((void**)&p_wff1, h_wff1);
    cudaGetSymbolAddress((void**)&p_wff2, h_wff2);
    cudaGetSymbolAddress((void**)&p_qkv,  h_qkv);
    cudaGetSymbolAddress((void**)&p_attn, h_attn);
    cudaGetSymbolAddress((void**)&p_x1h,  h_x1);
    cudaGetSymbolAddress((void**)&p_ff1,  h_ff1);
    cudaGetSymbolAddress((void**)&p_proj, s_proj);
    cudaGetSymbolAddress((void**)&p_x1f,  s_x1f);
    cudaGetSymbolAddress((void**)&p_ff2,  s_ff2);

    cudaFuncSetAttribute(gemm_h<0,1>, cudaFuncAttributeMaxDynamicSharedMemorySize, GEMM_SMEM);
    cudaFuncSetAttribute(gemm_h<0,0>, cudaFuncAttributeMaxDynamicSharedMemorySize, GEMM_SMEM);
    cudaFuncSetAttribute(gemm_h<1,1>, cudaFuncAttributeMaxDynamicSharedMemorySize, GEMM_SMEM);
    cudaFuncSetAttribute(flash_h,     cudaFuncAttributeMaxDynamicSharedMemorySize, FLASH_SMEM);

    // 0) fp32 -> fp16 conversions (single launch)
    conv_all<<<CNT / 256, 256>>>(
        (const float4*)x, (const float4*)w_qkv, (const float4*)w_out,
        (const float4*)w_ff1, (const float4*)w_ff2,
        (__half2*)p_hx, (__half2*)p_wqkv, (__half2*)p_wout,
        (__half2*)p_wff1, (__half2*)p_wff2);

    // 1) QKV projection (fp16 out)
    gemm_h<0,1><<<dim3(3 * E_ / 128, M_ / 128), 256, GEMM_SMEM>>>(
        p_hx, p_wqkv, b_qkv, p_qkv, M_, 3 * E_, E_);

    // 2) flash attention (fp16)
    flash_h<<<dim3(S_ / 64, B_ * H_), 256, FLASH_SMEM>>>(p_qkv, p_attn);

    // 3) output projection (fp32 out)
    gemm_h<0,0><<<dim3(E_ / 128, M_ / 128), 256, GEMM_SMEM>>>(
        p_attn, p_wout, b_out, p_proj, M_, E_, E_);

    // 4) LN1 (fp32 + fp16 out)
    ln_kernel<1><<<M_, 256>>>(x, p_proj, g1, be1, p_x1f, p_x1h);

    // 5) FF1 + GELU (fp16 out)
    gemm_h<1,1><<<dim3(FF_ / 128, M_ / 128), 256, GEMM_SMEM>>>(
        p_x1h, p_wff1, b_ff1, p_ff1, M_, FF_, E_);

    // 6) FF2 (fp32 out)
    gemm_h<0,0><<<dim3(E_ / 128, M_ / 128), 256, GEMM_SMEM>>>(
        p_ff1, p_wff2, b_ff2, p_ff2, M_, E_, FF_);

    // 7) LN2 -> output
    ln_kernel<0><<<M_, 256>>>(p_x1f, p_ff2, g2, be2, out, nullptr);
}

// round 13
// speedup vs baseline: 1.0946x; 1.0126x over previous
#include <cuda_runtime.h>
#include <cuda_fp16.h>
#include <math.h>
#include <stdint.h>

// Problem constants: B=2, S=2048, E=1024, H=16, HD=64
#define B_  2
#define S_  2048
#define E_  1024
#define H_  16
#define HD_ 64
#define M_  (B_*S_)     // 4096 tokens
#define FF_ (4*E_)      // 4096

// ---------------- scratch (static device globals) --------------------------
__device__ __half h_x   [M_ * E_];
__device__ __half h_wqkv[E_ * 3 * E_];
__device__ __half h_wout[E_ * E_];
__device__ __half h_wff1[E_ * FF_];
__device__ __half h_wff2[FF_ * E_];
__device__ __half h_qkv [M_ * 3 * E_];
__device__ __half h_attn[M_ * E_];
__device__ __half h_x1  [M_ * E_];
__device__ __half h_ff1 [M_ * FF_];
__device__ float  s_proj[M_ * E_];
__device__ float  s_x1f [M_ * E_];
__device__ float  s_ff2 [M_ * E_];

__device__ __forceinline__ float gelu_f(float v) {
    return 0.5f * v * (1.0f + erff(v * 0.70710678118654752f));
}
__device__ __forceinline__ uint32_t smem_u32(const void* p) {
    uint32_t a;
    asm("{ .reg .u64 t; cvta.to.shared.u64 t, %1; cvt.u32.u64 %0, t; }"
        : "=r"(a) : "l"(p));
    return a;
}
__device__ __forceinline__ void cpa16(uint32_t s, const void* g) {
    asm volatile("cp.async.cg.shared.global [%0], [%1], 16;" :: "r"(s), "l"(g) : "memory");
}
#define CP_COMMIT() asm volatile("cp.async.commit_group;" ::: "memory")
#define CP_WAIT0()  asm volatile("cp.async.wait_group 0;" ::: "memory")
#define CP_WAIT1()  asm volatile("cp.async.wait_group 1;" ::: "memory")

__device__ __forceinline__ void ldsm4(uint32_t& r0, uint32_t& r1, uint32_t& r2,
                                      uint32_t& r3, uint32_t addr) {
    asm volatile("ldmatrix.sync.aligned.m8n8.x4.shared.b16 {%0,%1,%2,%3}, [%4];"
                 : "=r"(r0), "=r"(r1), "=r"(r2), "=r"(r3) : "r"(addr));
}
__device__ __forceinline__ void ldsm4t(uint32_t& r0, uint32_t& r1, uint32_t& r2,
                                       uint32_t& r3, uint32_t addr) {
    asm volatile("ldmatrix.sync.aligned.m8n8.x4.trans.shared.b16 {%0,%1,%2,%3}, [%4];"
                 : "=r"(r0), "=r"(r1), "=r"(r2), "=r"(r3) : "r"(addr));
}
__device__ __forceinline__ void mma_f16(float* d, const uint32_t* a, const uint32_t* b) {
    asm volatile(
        "mma.sync.aligned.m16n8k16.row.col.f32.f16.f16.f32 "
        "{%0,%1,%2,%3}, {%4,%5,%6,%7}, {%8,%9}, {%0,%1,%2,%3};"
        : "+f"(d[0]), "+f"(d[1]), "+f"(d[2]), "+f"(d[3])
        : "r"(a[0]), "r"(a[1]), "r"(a[2]), "r"(a[3]), "r"(b[0]), "r"(b[1]));
}

// ---------------------------------------------------------------------------
// fp32 -> fp16 conversion, all 5 tensors in one launch
// ---------------------------------------------------------------------------
#define CN0 (M_*E_/4)
#define CN1 (E_*3*E_/4)
#define CN2 (E_*E_/4)
#define CN3 (E_*FF_/4)
#define CN4 (FF_*E_/4)
#define CNT (CN0+CN1+CN2+CN3+CN4)

__global__ void conv_all(
    const float4* __restrict__ x,   const float4* __restrict__ wqkv,
    const float4* __restrict__ wo,  const float4* __restrict__ wf1,
    const float4* __restrict__ wf2,
    __half2* dx, __half2* dqkv, __half2* dwo, __half2* df1, __half2* df2)
{
    int j = blockIdx.x * blockDim.x + threadIdx.x;
    const float4* s; __half2* d;
    if (j < CN0)              { s = x;    d = dx;   }
    else if ((j -= CN0) < CN1){ s = wqkv; d = dqkv; }
    else if ((j -= CN1) < CN2){ s = wo;   d = dwo;  }
    else if ((j -= CN2) < CN3){ s = wf1;  d = df1;  }
    else { j -= CN3;            s = wf2;  d = df2;  }
    float4 v = s[j];
    d[2*j]   = __floats2half2_rn(v.x, v.y);
    d[2*j+1] = __floats2half2_rn(v.z, v.w);
}

// ===========================================================================
// FP16 mma.sync GEMM: C[M,N] = A[M,K] @ B[K,N] + bias (+GELU).
// CTA 128x128, BK=64, 2-stage cp.async, 2 CTAs/SM. Warp tile 64x32 (2x4).
// A stage: 128 rows x 144B stride (18432B). B: 64 rows x 272B stride (17408B).
// ===========================================================================
#define GA_BYTES (128 * 144)         // 18432
#define GB_BYTES (64 * 272)          // 17408
#define GSTG (GA_BYTES + GB_BYTES)   // 35840
#define GEMM_SMEM (2 * GSTG)         // 71680

template<int ACT, int OUTH>
__global__ void __launch_bounds__(256, 2) gemm_h(
    const __half* __restrict__ A, const __half* __restrict__ Bm,
    const float* __restrict__ bias, void* __restrict__ Cv,
    int M, int N, int K)
{
    extern __shared__ char smraw[];
    const uint32_t sbase = smem_u32(smraw);
    const int tid = threadIdx.x, lane = tid & 31, wid = tid >> 5;
    const int wm = wid & 1, wn = wid >> 1;
    const int bm = blockIdx.y << 7, bn = blockIdx.x << 7;

    float acc[4][4][4];
    #pragma unroll
    for (int i = 0; i < 4; i++)
        #pragma unroll
        for (int j = 0; j < 4; j++)
            #pragma unroll
            for (int q = 0; q < 4; q++) acc[i][j][q] = 0.f;

    const __half* Abase = A + (size_t)bm * K;
    const __half* Bbase = Bm + bn;

    auto load_stage = [&](int kt, int slot) {
        const uint32_t a0 = sbase + (uint32_t)slot * GSTG;
        const uint32_t b0 = a0 + GA_BYTES;
        #pragma unroll
        for (int i = 0; i < 4; i++) {
            int idx = tid + (i << 8);
            int r = idx >> 3, c = idx & 7;            // 128 rows x 8 chunks
            cpa16(a0 + (uint32_t)(r * 144 + c * 16),
                  Abase + (size_t)r * K + kt * 64 + c * 8);
        }
        #pragma unroll
        for (int i = 0; i < 4; i++) {
            int idx = tid + (i << 8);
            int r = idx >> 4, c = idx & 15;           // 64 rows x 16 chunks
            cpa16(b0 + (uint32_t)(r * 272 + c * 16),
                  Bbase + (size_t)(kt * 64 + r) * N + c * 8);
        }
    };

    const uint32_t a_lane = (uint32_t)((lane & 15) * 144 + (lane >> 4) * 16);
    const int bK = ((lane >> 3) & 1) * 8 + (lane & 7);
    const int bN = ((lane >> 4) & 1) * 8;

    const int T = K >> 6;
    load_stage(0, 0);
    CP_COMMIT();

    for (int t = 0; t < T; ++t) {
        if (t + 1 < T) { load_stage(t + 1, (t + 1) & 1); CP_COMMIT(); }
        if (t + 1 < T) CP_WAIT1();
        else           CP_WAIT0();
        __syncthreads();

        const int slot = t & 1;
        const uint32_t aS = sbase + (uint32_t)slot * GSTG + (uint32_t)(wm * 64 * 144) + a_lane;
        const uint32_t bS = sbase + (uint32_t)slot * GSTG + GA_BYTES;

        #pragma unroll
        for (int kk = 0; kk < 4; kk++) {
            uint32_t af[4][4];
            #pragma unroll
            for (int mt = 0; mt < 4; mt++)
                ldsm4(af[mt][0], af[mt][1], af[mt][2], af[mt][3],
                      aS + (uint32_t)(mt * 16 * 144 + kk * 32));
            uint32_t bf[4][2];
            #pragma unroll
            for (int ntp = 0; ntp < 2; ntp++) {
                uint32_t r0, r1, r2, r3;
                uint32_t baddr = bS + (uint32_t)((kk * 16 + bK) * 272
                                + (wn * 32 + ntp * 16 + bN) * 2);
                ldsm4t(r0, r1, r2, r3, baddr);
                bf[2*ntp][0] = r0; bf[2*ntp][1] = r1;
                bf[2*ntp+1][0] = r2; bf[2*ntp+1][1] = r3;
            }
            #pragma unroll
            for (int mt = 0; mt < 4; mt++)
                #pragma unroll
                for (int nt = 0; nt < 4; nt++)
                    mma_f16(acc[mt][nt], af[mt], bf[nt]);
        }
        __syncthreads();
    }

    // epilogue: bias (+gelu), fp16 or fp32 out
    #pragma unroll
    for (int mt = 0; mt < 4; mt++) {
        #pragma unroll
        for (int half = 0; half < 2; half++) {
            const int r = bm + wm * 64 + mt * 16 + (lane >> 2) + half * 8;
            #pragma unroll
            for (int nt = 0; nt < 4; nt++) {
                const int c = bn + wn * 32 + nt * 8 + (lane & 3) * 2;
                float v0 = acc[mt][nt][half * 2 + 0] + bias[c];
                float v1 = acc[mt][nt][half * 2 + 1] + bias[c + 1];
                if (ACT) { v0 = gelu_f(v0); v1 = gelu_f(v1); }
                if (OUTH) {
                    __half* C = (__half*)Cv;
                    *(__half2*)(C + (size_t)r * N + c) = __floats2half2_rn(v0, v1);
                } else {
                    float* C = (float*)Cv;
                    *(float2*)(C + (size_t)r * N + c) = make_float2(v0, v1);
                }
            }
        }
    }
}

// ===========================================================================
// Flash attention, fp16 mma. CTA: one (b,h), 64 Q rows, 8 warps 2(M)x4(N).
// Q fragments hoisted out of the KV loop (loop-invariant).
// ===========================================================================
#define OFF_Q  0
#define OFF_K  9216
#define OFF_V  (9216 + 18432)
#define OFF_SF (9216 + 18432 + 18432)
#define OFF_PH (OFF_SF + 17408)
#define OFF_RW (OFF_PH + 9216)
#define FLASH_SMEM (OFF_RW + 768)

__global__ void __launch_bounds__(256, 2) flash_h(
    const __half* __restrict__ qkv, __half* __restrict__ attn)
{
    extern __shared__ char smraw[];
    const uint32_t base = smem_u32(smraw);
    const uint32_t QsU = base + OFF_Q, KsU = base + OFF_K, VsU = base + OFF_V;
    __half* Ph  = (__half*)(smraw + OFF_PH);
    float* Sf   = (float*)(smraw + OFF_SF);
    float* mrow = (float*)(smraw + OFF_RW);
    float* lrow = mrow + 64;
    float* arow = lrow + 64;
    const uint32_t PhU = base + OFF_PH;

    const int tid = threadIdx.x, lane = tid & 31, wid = tid >> 5;
    const int wm = wid & 1, wn = wid >> 1;
    const int q0 = blockIdx.x << 6;
    const int b  = blockIdx.y >> 4, h = blockIdx.y & 15;

    const __half* qb = qkv + (size_t)b * S_ * (3 * E_) + h * HD_;
    const __half* kb = qb + E_;
    const __half* vb = qb + 2 * E_;

    // Q tile + first K/V stage (one commit group)
    #pragma unroll
    for (int i = 0; i < 2; i++) {
        int idx = tid + (i << 8);
        int r = idx >> 3, c = idx & 7;
        cpa16(QsU + (uint32_t)(r * 144 + c * 16), qb + (size_t)(q0 + r) * (3 * E_) + c * 8);
    }
    auto load_kv = [&](int t, int s) {
        #pragma unroll
        for (int i = 0; i < 2; i++) {
            int idx = tid + (i << 8);
            int r = idx >> 3, c = idx & 7;
            size_t go = (size_t)(t * 64 + r) * (3 * E_) + c * 8;
            cpa16(KsU + (uint32_t)(s * 9216 + r * 144 + c * 16), kb + go);
            cpa16(VsU + (uint32_t)(s * 9216 + r * 144 + c * 16), vb + go);
        }
    };
    load_kv(0, 0);
    CP_COMMIT();
    if (tid < 64) { mrow[tid] = -1e30f; lrow[tid] = 0.f; }

    const uint32_t a_lane = (uint32_t)((lane & 15) * 144 + (lane >> 4) * 16);
    const int rh = lane >> 2, c2 = (lane & 3) * 2;
    const int kKey = ((lane >> 4) & 1) * 8 + (lane & 7);
    const int kDb  = ((lane >> 3) & 1) * 16;
    const int vKey = ((lane >> 3) & 1) * 8 + (lane & 7);
    const int vD   = ((lane >> 4) & 1) * 8;

    CP_WAIT0();
    __syncthreads();          // Q + KV0 ready, mrow/lrow initialized

    // hoist Q fragments (loop-invariant)
    uint32_t qf[4][2][4];
    #pragma unroll
    for (int kk = 0; kk < 4; kk++)
        #pragma unroll
        for (int mt = 0; mt < 2; mt++)
            ldsm4(qf[kk][mt][0], qf[kk][mt][1], qf[kk][mt][2], qf[kk][mt][3],
                  QsU + (uint32_t)((wm * 32 + mt * 16) * 144 + kk * 32) + a_lane);

    float O[2][2][4];
    #pragma unroll
    for (int a = 0; a < 2; a++)
        #pragma unroll
        for (int bb = 0; bb < 2; bb++)
            #pragma unroll
            for (int q = 0; q < 4; q++) O[a][bb][q] = 0.f;

    const int T = S_ / 64;
    for (int t = 0; t < T; ++t) {
        const int s = t & 1;
        if (t + 1 < T) { load_kv(t + 1, s ^ 1); CP_COMMIT(); }

        // ---- S = Q K^T ----
        float sf[2][2][4];
        #pragma unroll
        for (int a = 0; a < 2; a++)
            #pragma unroll
            for (int bb = 0; bb < 2; bb++)
                #pragma unroll
                for (int q = 0; q < 4; q++) sf[a][bb][q] = 0.f;

        #pragma unroll
        for (int kk = 0; kk < 4; kk++) {
            uint32_t r0, r1, r2, r3;
            uint32_t kaddr = KsU + (uint32_t)(s * 9216 + (wn * 16 + kKey) * 144
                             + kk * 32 + kDb);
            ldsm4(r0, r1, r2, r3, kaddr);
            uint32_t bf[2][2] = {{r0, r1}, {r2, r3}};
            #pragma unroll
            for (int mt = 0; mt < 2; mt++)
                #pragma unroll
                for (int nt = 0; nt < 2; nt++)
                    mma_f16(sf[mt][nt], qf[kk][mt], bf[nt]);
        }
        // scaled S -> Sf (fp32)
        #pragma unroll
        for (int mt = 0; mt < 2; mt++)
            #pragma unroll
            for (int nt = 0; nt < 2; nt++) {
                int row0 = wm * 32 + mt * 16 + rh;
                int col  = wn * 16 + nt * 8 + c2;
                *(float2*)&Sf[row0 * 68 + col] =
                    make_float2(sf[mt][nt][0] * 0.125f, sf[mt][nt][1] * 0.125f);
                *(float2*)&Sf[(row0 + 8) * 68 + col] =
                    make_float2(sf[mt][nt][2] * 0.125f, sf[mt][nt][3] * 0.125f);
            }
        __syncthreads();

        // ---- online softmax: 4 threads/row; write P fp16 ----
        {
            int row = tid >> 2;
            float* sr = Sf + row * 68 + (tid & 3) * 16;
            float4 v0 = *(float4*)(sr),     v1 = *(float4*)(sr + 4),
                   v2 = *(float4*)(sr + 8), v3 = *(float4*)(sr + 12);
            float mx = fmaxf(fmaxf(fmaxf(v0.x, v0.y), fmaxf(v0.z, v0.w)),
                             fmaxf(fmaxf(v1.x, v1.y), fmaxf(v1.z, v1.w)));
            mx = fmaxf(mx, fmaxf(fmaxf(fmaxf(v2.x, v2.y), fmaxf(v2.z, v2.w)),
                                 fmaxf(fmaxf(v3.x, v3.y), fmaxf(v3.z, v3.w))));
            mx = fmaxf(mx, __shfl_xor_sync(0xffffffffu, mx, 1));
            mx = fmaxf(mx, __shfl_xor_sync(0xffffffffu, mx, 2));
            float mo = mrow[row];
            float mn = fmaxf(mo, mx);
            v0.x = __expf(v0.x - mn); v0.y = __expf(v0.y - mn);
            v0.z = __expf(v0.z - mn); v0.w = __expf(v0.w - mn);
            v1.x = __expf(v1.x - mn); v1.y = __expf(v1.y - mn);
            v1.z = __expf(v1.z - mn); v1.w = __expf(v1.w - mn);
            v2.x = __expf(v2.x - mn); v2.y = __expf(v2.y - mn);
            v2.z = __expf(v2.z - mn); v2.w = __expf(v2.w - mn);
            v3.x = __expf(v3.x - mn); v3.y = __expf(v3.y - mn);
            v3.z = __expf(v3.z - mn); v3.w = __expf(v3.w - mn);
            __half2 hp[8];
            hp[0] = __floats2half2_rn(v0.x, v0.y); hp[1] = __floats2half2_rn(v0.z, v0.w);
            hp[2] = __floats2half2_rn(v1.x, v1.y); hp[3] = __floats2half2_rn(v1.z, v1.w);
            hp[4] = __floats2half2_rn(v2.x, v2.y); hp[5] = __floats2half2_rn(v2.z, v2.w);
            hp[6] = __floats2half2_rn(v3.x, v3.y); hp[7] = __floats2half2_rn(v3.z, v3.w);
            uint4* pdst = (uint4*)(Ph + row * 72 + (tid & 3) * 16);
            pdst[0] = *(uint4*)&hp[0];
            pdst[1] = *(uint4*)&hp[4];
            float su = v0.x + v0.y + v0.z + v0.w + v1.x + v1.y + v1.z + v1.w
                     + v2.x + v2.y + v2.z + v2.w + v3.x + v3.y + v3.z + v3.w;
            su += __shfl_xor_sync(0xffffffffu, su, 1);
            su += __shfl_xor_sync(0xffffffffu, su, 2);
            if ((tid & 3) == 0) {
                float al = __expf(mo - mn);
                arow[row] = al;
                lrow[row] = lrow[row] * al + su;
                mrow[row] = mn;
            }
        }
        __syncthreads();

        // ---- rescale O; O += P @ V ----
        #pragma unroll
        for (int mt = 0; mt < 2; mt++) {
            float a0 = arow[wm * 32 + mt * 16 + rh];
            float a1 = arow[wm * 32 + mt * 16 + 8 + rh];
            #pragma unroll
            for (int nt = 0; nt < 2; nt++) {
                O[mt][nt][0] *= a0; O[mt][nt][1] *= a0;
                O[mt][nt][2] *= a1; O[mt][nt][3] *= a1;
            }
        }
        #pragma unroll
        for (int kk = 0; kk < 4; kk++) {
            uint32_t af[2][4];
            #pragma unroll
            for (int mt = 0; mt < 2; mt++)
                ldsm4(af[mt][0], af[mt][1], af[mt][2], af[mt][3],
                      PhU + (uint32_t)((wm * 32 + mt * 16) * 144 + kk * 32) + a_lane);
            uint32_t r0, r1, r2, r3;
            uint32_t vaddr = VsU + (uint32_t)(s * 9216 + (kk * 16 + vKey) * 144
                             + (wn * 16 + vD) * 2);
            ldsm4t(r0, r1, r2, r3, vaddr);
            uint32_t bf[2][2] = {{r0, r1}, {r2, r3}};
            #pragma unroll
            for (int mt = 0; mt < 2; mt++)
                #pragma unroll
                for (int nt = 0; nt < 2; nt++)
                    mma_f16(O[mt][nt], af[mt], bf[nt]);
        }

        // KV t+1 ready + all warps done with slot s and Ph before next iter
        if (t + 1 < T) CP_WAIT0();
        __syncthreads();
    }

    // ---- normalize + write fp16 ----
    #pragma unroll
    for (int mt = 0; mt < 2; mt++) {
        int row0 = wm * 32 + mt * 16 + rh;
        float inv0 = 1.f / lrow[row0];
        float inv1 = 1.f / lrow[row0 + 8];
        #pragma unroll
        for (int nt = 0; nt < 2; nt++) {
            int col = h * HD_ + wn * 16 + nt * 8 + c2;
            *(__half2*)&attn[(size_t)(b * S_ + q0 + row0) * E_ + col] =
                __floats2half2_rn(O[mt][nt][0] * inv0, O[mt][nt][1] * inv0);
            *(__half2*)&attn[(size_t)(b * S_ + q0 + row0 + 8) * E_ + col] =
                __floats2half2_rn(O[mt][nt][2] * inv1, O[mt][nt][3] * inv1);
        }
    }
}

// ---------------------------------------------------------------------------
// Fused residual-add + LayerNorm; optional fp16 secondary output.
// ---------------------------------------------------------------------------
template<int WH>
__global__ void __launch_bounds__(256) ln_kernel(
    const float* __restrict__ a, const float* __restrict__ bsrc,
    const float* __restrict__ g, const float* __restrict__ be,
    float* __restrict__ out, __half* __restrict__ outh)
{
    const int tok = blockIdx.x;
    const int tid = threadIdx.x;
    const float* pa = a    + (size_t)tok * E_;
    const float* pb = bsrc + (size_t)tok * E_;

    float r[4]; float s = 0.f;
    #pragma unroll
    for (int i = 0; i < 4; i++) {
        int e = tid + (i << 8);
        r[i] = pa[e] + pb[e];
        s += r[i];
    }
    __shared__ float red[8];
    #pragma unroll
    for (int o = 16; o > 0; o >>= 1) s += __shfl_xor_sync(0xffffffffu, s, o);
    if ((tid & 31) == 0) red[tid >> 5] = s;
    __syncthreads();
    float tot = 0.f;
    #pragma unroll
    for (int w = 0; w < 8; w++) tot += red[w];
    const float mean = tot * (1.0f / E_);

    float vs = 0.f;
    #pragma unroll
    for (int i = 0; i < 4; i++) { float d = r[i] - mean; vs += d * d; }
    #pragma unroll
    for (int o = 16; o > 0; o >>= 1) vs += __shfl_xor_sync(0xffffffffu, vs, o);
    __syncthreads();
    if ((tid & 31) == 0) red[tid >> 5] = vs;
    __syncthreads();
    float vtot = 0.f;
    #pragma unroll
    for (int w = 0; w < 8; w++) vtot += red[w];
    const float rstd = rsqrtf(vtot * (1.0f / E_) + 1e-5f);

    #pragma unroll
    for (int i = 0; i < 4; i++) {
        int e = tid + (i << 8);
        float v = (r[i] - mean) * rstd * g[e] + be[e];
        out[(size_t)tok * E_ + e] = v;
        if (WH) outh[(size_t)tok * E_ + e] = __float2half(v);
    }
}

// ---------------------------------------------------------------------------
extern "C" void kernel_launch(void* const* d_in, const int* in_sizes, int n_in,
                              void* d_out, int out_size)
{
    const float* x     = (const float*)d_in[0];
    const float* w_qkv = (const float*)d_in[1];
    const float* b_qkv = (const float*)d_in[2];
    const float* w_out = (const float*)d_in[3];
    const float* b_out = (const float*)d_in[4];
    const float* w_ff1 = (const float*)d_in[5];
    const float* b_ff1 = (const float*)d_in[6];
    const float* w_ff2 = (const float*)d_in[7];
    const float* b_ff2 = (const float*)d_in[8];
    const float* g1    = (const float*)d_in[9];
    const float* be1   = (const float*)d_in[10];
    const float* g2    = (const float*)d_in[11];
    const float* be2   = (const float*)d_in[12];
    float* out = (float*)d_out;

    __half *p_hx, *p_wqkv, *p_wout, *p_wff1, *p_wff2;
    __half *p_qkv, *p_attn, *p_x1h, *p_ff1;
    float *p_proj, *p_x1f, *p_ff2;
    cudaGetSymbolAddress((void**)&p_hx,   h_x);
    cudaGetSymbolAddress((void**)&p_wqkv, h_wqkv);
    cudaGetSymbolAddress((void**)&p_wout, h_wout);
    cudaGetSymbolAddress((void**)&p_wff1, h_wff1);
    cudaGetSymbolAddress((void**)&p_wff2, h_wff2);
    cudaGetSymbolAddress((void**)&p_qkv,  h_qkv);
    cudaGetSymbolAddress((void**)&p_attn, h_attn);
    cudaGetSymbolAddress((void**)&p_x1h,  h_x1);
    cudaGetSymbolAddress((void**)&p_ff1,  h_ff1);
    cudaGetSymbolAddress((void**)&p_proj, s_proj);
    cudaGetSymbolAddress((void**)&p_x1f,  s_x1f);
    cudaGetSymbolAddress((void**)&p_ff2,  s_ff2);

    cudaFuncSetAttribute(gemm_h<0,1>, cudaFuncAttributeMaxDynamicSharedMemorySize, GEMM_SMEM);
    cudaFuncSetAttribute(gemm_h<0,0>, cudaFuncAttributeMaxDynamicSharedMemorySize, GEMM_SMEM);
    cudaFuncSetAttribute(gemm_h<1,1>, cudaFuncAttributeMaxDynamicSharedMemorySize, GEMM_SMEM);
    cudaFuncSetAttribute(flash_h,     cudaFuncAttributeMaxDynamicSharedMemorySize, FLASH_SMEM);

    // 0) fp32 -> fp16 conversions (single launch)
    conv_all<<<CNT / 256, 256>>>(
        (const float4*)x, (const float4*)w_qkv, (const float4*)w_out,
        (const float4*)w_ff1, (const float4*)w_ff2,
        (__half2*)p_hx, (__half2*)p_wqkv, (__half2*)p_wout,
        (__half2*)p_wff1, (__half2*)p_wff2);

    // 1) QKV projection (fp16 out)
    gemm_h<0,1><<<dim3(3 * E_ / 128, M_ / 128), 256, GEMM_SMEM>>>(
        p_hx, p_wqkv, b_qkv, p_qkv, M_, 3 * E_, E_);

    // 2) flash attention (fp16)
    flash_h<<<dim3(S_ / 64, B_ * H_), 256, FLASH_SMEM>>>(p_qkv, p_attn);

    // 3) output projection (fp32 out)
    gemm_h<0,0><<<dim3(E_ / 128, M_ / 128), 256, GEMM_SMEM>>>(
        p_attn, p_wout, b_out, p_proj, M_, E_, E_);

    // 4) LN1 (fp32 + fp16 out)
    ln_kernel<1><<<M_, 256>>>(x, p_proj, g1, be1, p_x1f, p_x1h);

    // 5) FF1 + GELU (fp16 out)
    gemm_h<1,1><<<dim3(FF_ / 128, M_ / 128), 256, GEMM_SMEM>>>(
        p_x1h, p_wff1, b_ff1, p_ff1, M_, FF_, E_);

    // 6) FF2 (fp32 out)
    gemm_h<0,0><<<dim3(E_ / 128, M_ / 128), 256, GEMM_SMEM>>>(
        p_ff1, p_wff2, b_ff2, p_ff2, M_, E_, FF_);

    // 7) LN2 -> output
    ln_kernel<0><<<M_, 256>>>(p_x1f, p_ff2, g2, be2, out, nullptr);
}

// round 15
// speedup vs baseline: 1.1052x; 1.0096x over previous
#include <cuda_runtime.h>
#include <cuda_fp16.h>
#include <math.h>
#include <stdint.h>

// Problem constants: B=2, S=2048, E=1024, H=16, HD=64
#define B_  2
#define S_  2048
#define E_  1024
#define H_  16
#define HD_ 64
#define M_  (B_*S_)     // 4096 tokens
#define FF_ (4*E_)      // 4096

// ---------------- scratch (static device globals) --------------------------
__device__ __half h_x   [M_ * E_];
__device__ __half h_wqkv[E_ * 3 * E_];
__device__ __half h_wout[E_ * E_];
__device__ __half h_wff1[E_ * FF_];
__device__ __half h_wff2[FF_ * E_];
__device__ __half h_qkv [M_ * 3 * E_];
__device__ __half h_attn[M_ * E_];
__device__ __half h_x1  [M_ * E_];
__device__ __half h_ff1 [M_ * FF_];
__device__ float  s_proj[M_ * E_];
__device__ float  s_x1f [M_ * E_];
__device__ float  s_ff2 [M_ * E_];

__device__ __forceinline__ float gelu_f(float v) {
    return 0.5f * v * (1.0f + erff(v * 0.70710678118654752f));
}
__device__ __forceinline__ uint32_t smem_u32(const void* p) {
    uint32_t a;
    asm("{ .reg .u64 t; cvta.to.shared.u64 t, %1; cvt.u32.u64 %0, t; }"
        : "=r"(a) : "l"(p));
    return a;
}
__device__ __forceinline__ void cpa16(uint32_t s, const void* g) {
    asm volatile("cp.async.cg.shared.global [%0], [%1], 16;" :: "r"(s), "l"(g) : "memory");
}
#define CP_COMMIT() asm volatile("cp.async.commit_group;" ::: "memory")
#define CP_WAIT0()  asm volatile("cp.async.wait_group 0;" ::: "memory")
#define CP_WAIT1()  asm volatile("cp.async.wait_group 1;" ::: "memory")

__device__ __forceinline__ void ldsm4(uint32_t& r0, uint32_t& r1, uint32_t& r2,
                                      uint32_t& r3, uint32_t addr) {
    asm volatile("ldmatrix.sync.aligned.m8n8.x4.shared.b16 {%0,%1,%2,%3}, [%4];"
                 : "=r"(r0), "=r"(r1), "=r"(r2), "=r"(r3) : "r"(addr));
}
__device__ __forceinline__ void ldsm4t(uint32_t& r0, uint32_t& r1, uint32_t& r2,
                                       uint32_t& r3, uint32_t addr) {
    asm volatile("ldmatrix.sync.aligned.m8n8.x4.trans.shared.b16 {%0,%1,%2,%3}, [%4];"
                 : "=r"(r0), "=r"(r1), "=r"(r2), "=r"(r3) : "r"(addr));
}
__device__ __forceinline__ void mma_f16(float* d, const uint32_t* a, const uint32_t* b) {
    asm volatile(
        "mma.sync.aligned.m16n8k16.row.col.f32.f16.f16.f32 "
        "{%0,%1,%2,%3}, {%4,%5,%6,%7}, {%8,%9}, {%0,%1,%2,%3};"
        : "+f"(d[0]), "+f"(d[1]), "+f"(d[2]), "+f"(d[3])
        : "r"(a[0]), "r"(a[1]), "r"(a[2]), "r"(a[3]), "r"(b[0]), "r"(b[1]));
}

// ---------------------------------------------------------------------------
// fp32 -> fp16 conversion, all 5 tensors in one launch
// ---------------------------------------------------------------------------
#define CN0 (M_*E_/4)
#define CN1 (E_*3*E_/4)
#define CN2 (E_*E_/4)
#define CN3 (E_*FF_/4)
#define CN4 (FF_*E_/4)
#define CNT (CN0+CN1+CN2+CN3+CN4)

__global__ void conv_all(
    const float4* __restrict__ x,   const float4* __restrict__ wqkv,
    const float4* __restrict__ wo,  const float4* __restrict__ wf1,
    const float4* __restrict__ wf2,
    __half2* dx, __half2* dqkv, __half2* dwo, __half2* df1, __half2* df2)
{
    int j = blockIdx.x * blockDim.x + threadIdx.x;
    const float4* s; __half2* d;
    if (j < CN0)              { s = x;    d = dx;   }
    else if ((j -= CN0) < CN1){ s = wqkv; d = dqkv; }
    else if ((j -= CN1) < CN2){ s = wo;   d = dwo;  }
    else if ((j -= CN2) < CN3){ s = wf1;  d = df1;  }
    else { j -= CN3;            s = wf2;  d = df2;  }
    float4 v = s[j];
    d[2*j]   = __floats2half2_rn(v.x, v.y);
    d[2*j+1] = __floats2half2_rn(v.z, v.w);
}

// ===========================================================================
// FP16 mma.sync GEMM: C[M,N] = A[M,K] @ B[K,N] + bias (+GELU).
// CTA 128x128, BK=64, 3-stage cp.async, single sync/iter, 2 CTAs/SM.
// Warp tile 64x32 (2x4 warps).
// A stage: 128 rows x 144B stride (18432B). B: 64 rows x 272B stride (17408B).
// ===========================================================================
#define GA_BYTES (128 * 144)         // 18432
#define GB_BYTES (64 * 272)          // 17408
#define GSTG (GA_BYTES + GB_BYTES)   // 35840
#define GEMM_SMEM (3 * GSTG)         // 107520

template<int ACT, int OUTH>
__global__ void __launch_bounds__(256, 2) gemm_h(
    const __half* __restrict__ A, const __half* __restrict__ Bm,
    const float* __restrict__ bias, void* __restrict__ Cv,
    int M, int N, int K)
{
    extern __shared__ char smraw[];
    const uint32_t sbase = smem_u32(smraw);
    const int tid = threadIdx.x, lane = tid & 31, wid = tid >> 5;
    const int wm = wid & 1, wn = wid >> 1;
    const int bm = blockIdx.y << 7, bn = blockIdx.x << 7;

    float acc[4][4][4];
    #pragma unroll
    for (int i = 0; i < 4; i++)
        #pragma unroll
        for (int j = 0; j < 4; j++)
            #pragma unroll
            for (int q = 0; q < 4; q++) acc[i][j][q] = 0.f;

    const __half* Abase = A + (size_t)bm * K;
    const __half* Bbase = Bm + bn;

    auto load_stage = [&](int kt, int slot) {
        const uint32_t a0 = sbase + (uint32_t)slot * GSTG;
        const uint32_t b0 = a0 + GA_BYTES;
        #pragma unroll
        for (int i = 0; i < 4; i++) {
            int idx = tid + (i << 8);
            int r = idx >> 3, c = idx & 7;            // 128 rows x 8 chunks
            cpa16(a0 + (uint32_t)(r * 144 + c * 16),
                  Abase + (size_t)r * K + kt * 64 + c * 8);
        }
        #pragma unroll
        for (int i = 0; i < 4; i++) {
            int idx = tid + (i << 8);
            int r = idx >> 4, c = idx & 15;           // 64 rows x 16 chunks
            cpa16(b0 + (uint32_t)(r * 272 + c * 16),
                  Bbase + (size_t)(kt * 64 + r) * N + c * 8);
        }
    };

    const uint32_t a_lane = (uint32_t)((lane & 15) * 144 + (lane >> 4) * 16);
    const int bK = ((lane >> 3) & 1) * 8 + (lane & 7);
    const int bN = ((lane >> 4) & 1) * 8;

    const int T = K >> 6;
    load_stage(0, 0); CP_COMMIT();
    load_stage(1, 1); CP_COMMIT();

    for (int t = 0; t < T; ++t) {
        CP_WAIT1();          // stage t complete; stage t+1 still in flight
        __syncthreads();     // all warps done reading slot (t+2)%3 (iter t-1)
        if (t + 2 < T) load_stage(t + 2, (t + 2) % 3);
        CP_COMMIT();         // unconditional: uniform group counting

        const int slot = t % 3;
        const uint32_t aS = sbase + (uint32_t)slot * GSTG + (uint32_t)(wm * 64 * 144) + a_lane;
        const uint32_t bS = sbase + (uint32_t)slot * GSTG + GA_BYTES;

        #pragma unroll
        for (int kk = 0; kk < 4; kk++) {
            uint32_t af[4][4];
            #pragma unroll
            for (int mt = 0; mt < 4; mt++)
                ldsm4(af[mt][0], af[mt][1], af[mt][2], af[mt][3],
                      aS + (uint32_t)(mt * 16 * 144 + kk * 32));
            uint32_t bf[4][2];
            #pragma unroll
            for (int ntp = 0; ntp < 2; ntp++) {
                uint32_t r0, r1, r2, r3;
                uint32_t baddr = bS + (uint32_t)((kk * 16 + bK) * 272
                                + (wn * 32 + ntp * 16 + bN) * 2);
                ldsm4t(r0, r1, r2, r3, baddr);
                bf[2*ntp][0] = r0; bf[2*ntp][1] = r1;
                bf[2*ntp+1][0] = r2; bf[2*ntp+1][1] = r3;
            }
            #pragma unroll
            for (int mt = 0; mt < 4; mt++)
                #pragma unroll
                for (int nt = 0; nt < 4; nt++)
                    mma_f16(acc[mt][nt], af[mt], bf[nt]);
        }
    }

    // epilogue: bias (+gelu), fp16 or fp32 out
    #pragma unroll
    for (int mt = 0; mt < 4; mt++) {
        #pragma unroll
        for (int half = 0; half < 2; half++) {
            const int r = bm + wm * 64 + mt * 16 + (lane >> 2) + half * 8;
            #pragma unroll
            for (int nt = 0; nt < 4; nt++) {
                const int c = bn + wn * 32 + nt * 8 + (lane & 3) * 2;
                float v0 = acc[mt][nt][half * 2 + 0] + bias[c];
                float v1 = acc[mt][nt][half * 2 + 1] + bias[c + 1];
                if (ACT) { v0 = gelu_f(v0); v1 = gelu_f(v1); }
                if (OUTH) {
                    __half* C = (__half*)Cv;
                    *(__half2*)(C + (size_t)r * N + c) = __floats2half2_rn(v0, v1);
                } else {
                    float* C = (float*)Cv;
                    *(float2*)(C + (size_t)r * N + c) = make_float2(v0, v1);
                }
            }
        }
    }
}

// ===========================================================================
// Flash attention, fp16 mma. CTA: one (b,h), 64 Q rows, 8 warps 2(M)x4(N).
// Q fragments hoisted out of the KV loop (loop-invariant).
// ===========================================================================
#define OFF_Q  0
#define OFF_K  9216
#define OFF_V  (9216 + 18432)
#define OFF_SF (9216 + 18432 + 18432)
#define OFF_PH (OFF_SF + 17408)
#define OFF_RW (OFF_PH + 9216)
#define FLASH_SMEM (OFF_RW + 768)

__global__ void __launch_bounds__(256, 2) flash_h(
    const __half* __restrict__ qkv, __half* __restrict__ attn)
{
    extern __shared__ char smraw[];
    const uint32_t base = smem_u32(smraw);
    const uint32_t QsU = base + OFF_Q, KsU = base + OFF_K, VsU = base + OFF_V;
    __half* Ph  = (__half*)(smraw + OFF_PH);
    float* Sf   = (float*)(smraw + OFF_SF);
    float* mrow = (float*)(smraw + OFF_RW);
    float* lrow = mrow + 64;
    float* arow = lrow + 64;
    const uint32_t PhU = base + OFF_PH;

    const int tid = threadIdx.x, lane = tid & 31, wid = tid >> 5;
    const int wm = wid & 1, wn = wid >> 1;
    const int q0 = blockIdx.x << 6;
    const int b  = blockIdx.y >> 4, h = blockIdx.y & 15;

    const __half* qb = qkv + (size_t)b * S_ * (3 * E_) + h * HD_;
    const __half* kb = qb + E_;
    const __half* vb = qb + 2 * E_;

    // Q tile + first K/V stage (one commit group)
    #pragma unroll
    for (int i = 0; i < 2; i++) {
        int idx = tid + (i << 8);
        int r = idx >> 3, c = idx & 7;
        cpa16(QsU + (uint32_t)(r * 144 + c * 16), qb + (size_t)(q0 + r) * (3 * E_) + c * 8);
    }
    auto load_kv = [&](int t, int s) {
        #pragma unroll
        for (int i = 0; i < 2; i++) {
            int idx = tid + (i << 8);
            int r = idx >> 3, c = idx & 7;
            size_t go = (size_t)(t * 64 + r) * (3 * E_) + c * 8;
            cpa16(KsU + (uint32_t)(s * 9216 + r * 144 + c * 16), kb + go);
            cpa16(VsU + (uint32_t)(s * 9216 + r * 144 + c * 16), vb + go);
        }
    };
    load_kv(0, 0);
    CP_COMMIT();
    if (tid < 64) { mrow[tid] = -1e30f; lrow[tid] = 0.f; }

    const uint32_t a_lane = (uint32_t)((lane & 15) * 144 + (lane >> 4) * 16);
    const int rh = lane >> 2, c2 = (lane & 3) * 2;
    const int kKey = ((lane >> 4) & 1) * 8 + (lane & 7);
    const int kDb  = ((lane >> 3) & 1) * 16;
    const int vKey = ((lane >> 3) & 1) * 8 + (lane & 7);
    const int vD   = ((lane >> 4) & 1) * 8;

    CP_WAIT0();
    __syncthreads();          // Q + KV0 ready, mrow/lrow initialized

    // hoist Q fragments (loop-invariant)
    uint32_t qf[4][2][4];
    #pragma unroll
    for (int kk = 0; kk < 4; kk++)
        #pragma unroll
        for (int mt = 0; mt < 2; mt++)
            ldsm4(qf[kk][mt][0], qf[kk][mt][1], qf[kk][mt][2], qf[kk][mt][3],
                  QsU + (uint32_t)((wm * 32 + mt * 16) * 144 + kk * 32) + a_lane);

    float O[2][2][4];
    #pragma unroll
    for (int a = 0; a < 2; a++)
        #pragma unroll
        for (int bb = 0; bb < 2; bb++)
            #pragma unroll
            for (int q = 0; q < 4; q++) O[a][bb][q] = 0.f;

    const int T = S_ / 64;
    for (int t = 0; t < T; ++t) {
        const int s = t & 1;
        if (t + 1 < T) { load_kv(t + 1, s ^ 1); CP_COMMIT(); }

        // ---- S = Q K^T ----
        float sf[2][2][4];
        #pragma unroll
        for (int a = 0; a < 2; a++)
            #pragma unroll
            for (int bb = 0; bb < 2; bb++)
                #pragma unroll
                for (int q = 0; q < 4; q++) sf[a][bb][q] = 0.f;

        #pragma unroll
        for (int kk = 0; kk < 4; kk++) {
            uint32_t r0, r1, r2, r3;
            uint32_t kaddr = KsU + (uint32_t)(s * 9216 + (wn * 16 + kKey) * 144
                             + kk * 32 + kDb);
            ldsm4(r0, r1, r2, r3, kaddr);
            uint32_t bf[2][2] = {{r0, r1}, {r2, r3}};
            #pragma unroll
            for (int mt = 0; mt < 2; mt++)
                #pragma unroll
                for (int nt = 0; nt < 2; nt++)
                    mma_f16(sf[mt][nt], qf[kk][mt], bf[nt]);
        }
        // scaled S -> Sf (fp32)
        #pragma unroll
        for (int mt = 0; mt < 2; mt++)
            #pragma unroll
            for (int nt = 0; nt < 2; nt++) {
                int row0 = wm * 32 + mt * 16 + rh;
                int col  = wn * 16 + nt * 8 + c2;
                *(float2*)&Sf[row0 * 68 + col] =
                    make_float2(sf[mt][nt][0] * 0.125f, sf[mt][nt][1] * 0.125f);
                *(float2*)&Sf[(row0 + 8) * 68 + col] =
                    make_float2(sf[mt][nt][2] * 0.125f, sf[mt][nt][3] * 0.125f);
            }
        __syncthreads();

        // ---- online softmax: 4 threads/row; write P fp16 ----
        {
            int row = tid >> 2;
            float* sr = Sf + row * 68 + (tid & 3) * 16;
            float4 v0 = *(float4*)(sr),     v1 = *(float4*)(sr + 4),
                   v2 = *(float4*)(sr + 8), v3 = *(float4*)(sr + 12);
            float mx = fmaxf(fmaxf(fmaxf(v0.x, v0.y), fmaxf(v0.z, v0.w)),
                             fmaxf(fmaxf(v1.x, v1.y), fmaxf(v1.z, v1.w)));
            mx = fmaxf(mx, fmaxf(fmaxf(fmaxf(v2.x, v2.y), fmaxf(v2.z, v2.w)),
                                 fmaxf(fmaxf(v3.x, v3.y), fmaxf(v3.z, v3.w))));
            mx = fmaxf(mx, __shfl_xor_sync(0xffffffffu, mx, 1));
            mx = fmaxf(mx, __shfl_xor_sync(0xffffffffu, mx, 2));
            float mo = mrow[row];
            float mn = fmaxf(mo, mx);
            v0.x = __expf(v0.x - mn); v0.y = __expf(v0.y - mn);
            v0.z = __expf(v0.z - mn); v0.w = __expf(v0.w - mn);
            v1.x = __expf(v1.x - mn); v1.y = __expf(v1.y - mn);
            v1.z = __expf(v1.z - mn); v1.w = __expf(v1.w - mn);
            v2.x = __expf(v2.x - mn); v2.y = __expf(v2.y - mn);
            v2.z = __expf(v2.z - mn); v2.w = __expf(v2.w - mn);
            v3.x = __expf(v3.x - mn); v3.y = __expf(v3.y - mn);
            v3.z = __expf(v3.z - mn); v3.w = __expf(v3.w - mn);
            __half2 hp[8];
            hp[0] = __floats2half2_rn(v0.x, v0.y); hp[1] = __floats2half2_rn(v0.z, v0.w);
            hp[2] = __floats2half2_rn(v1.x, v1.y); hp[3] = __floats2half2_rn(v1.z, v1.w);
            hp[4] = __floats2half2_rn(v2.x, v2.y); hp[5] = __floats2half2_rn(v2.z, v2.w);
            hp[6] = __floats2half2_rn(v3.x, v3.y); hp[7] = __floats2half2_rn(v3.z, v3.w);
            uint4* pdst = (uint4*)(Ph + row * 72 + (tid & 3) * 16);
            pdst[0] = *(uint4*)&hp[0];
            pdst[1] = *(uint4*)&hp[4];
            float su = v0.x + v0.y + v0.z + v0.w + v1.x + v1.y + v1.z + v1.w
                     + v2.x + v2.y + v2.z + v2.w + v3.x + v3.y + v3.z + v3.w;
            su += __shfl_xor_sync(0xffffffffu, su, 1);
            su += __shfl_xor_sync(0xffffffffu, su, 2);
            if ((tid & 3) == 0) {
                float al = __expf(mo - mn);
                arow[row] = al;
                lrow[row] = lrow[row] * al + su;
                mrow[row] = mn;
            }
        }
        __syncthreads();

        // ---- rescale O; O += P @ V ----
        #pragma unroll
        for (int mt = 0; mt < 2; mt++) {
            float a0 = arow[wm * 32 + mt * 16 + rh];
            float a1 = arow[wm * 32 + mt * 16 + 8 + rh];
            #pragma unroll
            for (int nt = 0; nt < 2; nt++) {
                O[mt][nt][0] *= a0; O[mt][nt][1] *= a0;
                O[mt][nt][2] *= a1; O[mt][nt][3] *= a1;
            }
        }
        #pragma unroll
        for (int kk = 0; kk < 4; kk++) {
            uint32_t af[2][4];
            #pragma unroll
            for (int mt = 0; mt < 2; mt++)
                ldsm4(af[mt][0], af[mt][1], af[mt][2], af[mt][3],
                      PhU + (uint32_t)((wm * 32 + mt * 16) * 144 + kk * 32) + a_lane);
            uint32_t r0, r1, r2, r3;
            uint32_t vaddr = VsU + (uint32_t)(s * 9216 + (kk * 16 + vKey) * 144
                             + (wn * 16 + vD) * 2);
            ldsm4t(r0, r1, r2, r3, vaddr);
            uint32_t bf[2][2] = {{r0, r1}, {r2, r3}};
            #pragma unroll
            for (int mt = 0; mt < 2; mt++)
                #pragma unroll
                for (int nt = 0; nt < 2; nt++)
                    mma_f16(O[mt][nt], af[mt], bf[nt]);
        }

        // KV t+1 ready + all warps done with slot s and Ph before next iter
        if (t + 1 < T) CP_WAIT0();
        __syncthreads();
    }

    // ---- normalize + write fp16 ----
    #pragma unroll
    for (int mt = 0; mt < 2; mt++) {
        int row0 = wm * 32 + mt * 16 + rh;
        float inv0 = 1.f / lrow[row0];
        float inv1 = 1.f / lrow[row0 + 8];
        #pragma unroll
        for (int nt = 0; nt < 2; nt++) {
            int col = h * HD_ + wn * 16 + nt * 8 + c2;
            *(__half2*)&attn[(size_t)(b * S_ + q0 + row0) * E_ + col] =
                __floats2half2_rn(O[mt][nt][0] * inv0, O[mt][nt][1] * inv0);
            *(__half2*)&attn[(size_t)(b * S_ + q0 + row0 + 8) * E_ + col] =
                __floats2half2_rn(O[mt][nt][2] * inv1, O[mt][nt][3] * inv1);
        }
    }
}

// ---------------------------------------------------------------------------
// Fused residual-add + LayerNorm; optional fp16 secondary output.
// ---------------------------------------------------------------------------
template<int WH>
__global__ void __launch_bounds__(256) ln_kernel(
    const float* __restrict__ a, const float* __restrict__ bsrc,
    const float* __restrict__ g, const float* __restrict__ be,
    float* __restrict__ out, __half* __restrict__ outh)
{
    const int tok = blockIdx.x;
    const int tid = threadIdx.x;
    const float* pa = a    + (size_t)tok * E_;
    const float* pb = bsrc + (size_t)tok * E_;

    float r[4]; float s = 0.f;
    #pragma unroll
    for (int i = 0; i < 4; i++) {
        int e = tid + (i << 8);
        r[i] = pa[e] + pb[e];
        s += r[i];
    }
    __shared__ float red[8];
    #pragma unroll
    for (int o = 16; o > 0; o >>= 1) s += __shfl_xor_sync(0xffffffffu, s, o);
    if ((tid & 31) == 0) red[tid >> 5] = s;
    __syncthreads();
    float tot = 0.f;
    #pragma unroll
    for (int w = 0; w < 8; w++) tot += red[w];
    const float mean = tot * (1.0f / E_);

    float vs = 0.f;
    #pragma unroll
    for (int i = 0; i < 4; i++) { float d = r[i] - mean; vs += d * d; }
    #pragma unroll
    for (int o = 16; o > 0; o >>= 1) vs += __shfl_xor_sync(0xffffffffu, vs, o);
    __syncthreads();
    if ((tid & 31) == 0) red[tid >> 5] = vs;
    __syncthreads();
    float vtot = 0.f;
    #pragma unroll
    for (int w = 0; w < 8; w++) vtot += red[w];
    const float rstd = rsqrtf(vtot * (1.0f / E_) + 1e-5f);

    #pragma unroll
    for (int i = 0; i < 4; i++) {
        int e = tid + (i << 8);
        float v = (r[i] - mean) * rstd * g[e] + be[e];
        out[(size_t)tok * E_ + e] = v;
        if (WH) outh[(size_t)tok * E_ + e] = __float2half(v);
    }
}

// ---------------------------------------------------------------------------
extern "C" void kernel_launch(void* const* d_in, const int* in_sizes, int n_in,
                              void* d_out, int out_size)
{
    const float* x     = (const float*)d_in[0];
    const float* w_qkv = (const float*)d_in[1];
    const float* b_qkv = (const float*)d_in[2];
    const float* w_out = (const float*)d_in[3];
    const float* b_out = (const float*)d_in[4];
    const float* w_ff1 = (const float*)d_in[5];
    const float* b_ff1 = (const float*)d_in[6];
    const float* w_ff2 = (const float*)d_in[7];
    const float* b_ff2 = (const float*)d_in[8];
    const float* g1    = (const float*)d_in[9];
    const float* be1   = (const float*)d_in[10];
    const float* g2    = (const float*)d_in[11];
    const float* be2   = (const float*)d_in[12];
    float* out = (float*)d_out;

    __half *p_hx, *p_wqkv, *p_wout, *p_wff1, *p_wff2;
    __half *p_qkv, *p_attn, *p_x1h, *p_ff1;
    float *p_proj, *p_x1f, *p_ff2;
    cudaGetSymbolAddress((void**)&p_hx,   h_x);
    cudaGetSymbolAddress((void**)&p_wqkv, h_wqkv);
    cudaGetSymbolAddress((void**)&p_wout, h_wout);
    cudaGetSymbolAddress((void**)&p_wff1, h_wff1);
    cudaGetSymbolAddress((void**)&p_wff2, h_wff2);
    cudaGetSymbolAddress((void**)&p_qkv,  h_qkv);
    cudaGetSymbolAddress((void**)&p_attn, h_attn);
    cudaGetSymbolAddress((void**)&p_x1h,  h_x1);
    cudaGetSymbolAddress((void**)&p_ff1,  h_ff1);
    cudaGetSymbolAddress((void**)&p_proj, s_proj);
    cudaGetSymbolAddress((void**)&p_x1f,  s_x1f);
    cudaGetSymbolAddress((void**)&p_ff2,  s_ff2);

    cudaFuncSetAttribute(gemm_h<0,1>, cudaFuncAttributeMaxDynamicSharedMemorySize, GEMM_SMEM);
    cudaFuncSetAttribute(gemm_h<0,0>, cudaFuncAttributeMaxDynamicSharedMemorySize, GEMM_SMEM);
    cudaFuncSetAttribute(gemm_h<1,1>, cudaFuncAttributeMaxDynamicSharedMemorySize, GEMM_SMEM);
    cudaFuncSetAttribute(flash_h,     cudaFuncAttributeMaxDynamicSharedMemorySize, FLASH_SMEM);

    // 0) fp32 -> fp16 conversions (single launch)
    conv_all<<<CNT / 256, 256>>>(
        (const float4*)x, (const float4*)w_qkv, (const float4*)w_out,
        (const float4*)w_ff1, (const float4*)w_ff2,
        (__half2*)p_hx, (__half2*)p_wqkv, (__half2*)p_wout,
        (__half2*)p_wff1, (__half2*)p_wff2);

    // 1) QKV projection (fp16 out)
    gemm_h<0,1><<<dim3(3 * E_ / 128, M_ / 128), 256, GEMM_SMEM>>>(
        p_hx, p_wqkv, b_qkv, p_qkv, M_, 3 * E_, E_);

    // 2) flash attention (fp16)
    flash_h<<<dim3(S_ / 64, B_ * H_), 256, FLASH_SMEM>>>(p_qkv, p_attn);

    // 3) output projection (fp32 out)
    gemm_h<0,0><<<dim3(E_ / 128, M_ / 128), 256, GEMM_SMEM>>>(
        p_attn, p_wout, b_out, p_proj, M_, E_, E_);

    // 4) LN1 (fp32 + fp16 out)
    ln_kernel<1><<<M_, 256>>>(x, p_proj, g1, be1, p_x1f, p_x1h);

    // 5) FF1 + GELU (fp16 out)
    gemm_h<1,1><<<dim3(FF_ / 128, M_ / 128), 256, GEMM_SMEM>>>(
        p_x1h, p_wff1, b_ff1, p_ff1, M_, FF_, E_);

    // 6) FF2 (fp32 out)
    gemm_h<0,0><<<dim3(E_ / 128, M_ / 128), 256, GEMM_SMEM>>>(
        p_ff1, p_wff2, b_ff2, p_ff2, M_, E_, FF_);

    // 7) LN2 -> output
    ln_kernel<0><<<M_, 256>>>(p_x1f, p_ff2, g2, be2, out, nullptr);
}

// round 16
// speedup vs baseline: 1.1645x; 1.0537x over previous
#include <cuda_runtime.h>
#include <cuda_fp16.h>
#include <math.h>
#include <stdint.h>

// Problem constants: B=2, S=2048, E=1024, H=16, HD=64
#define B_  2
#define S_  2048
#define E_  1024
#define H_  16
#define HD_ 64
#define M_  (B_*S_)     // 4096 tokens
#define FF_ (4*E_)      // 4096

// ---------------- scratch (static device globals) --------------------------
__device__ __half h_x   [M_ * E_];
__device__ __half h_wqkv[E_ * 3 * E_];
__device__ __half h_wout[E_ * E_];
__device__ __half h_wff1[E_ * FF_];
__device__ __half h_wff2[FF_ * E_];
__device__ __half h_qkv [M_ * 3 * E_];
__device__ __half h_attn[M_ * E_];
__device__ __half h_x1  [M_ * E_];
__device__ __half h_ff1 [M_ * FF_];
__device__ float  s_proj[M_ * E_];
__device__ float  s_x1f [M_ * E_];
__device__ float  s_ff2 [M_ * E_];

__device__ __forceinline__ float gelu_f(float v) {
    return 0.5f * v * (1.0f + erff(v * 0.70710678118654752f));
}
__device__ __forceinline__ uint32_t smem_u32(const void* p) {
    uint32_t a;
    asm("{ .reg .u64 t; cvta.to.shared.u64 t, %1; cvt.u32.u64 %0, t; }"
        : "=r"(a) : "l"(p));
    return a;
}
__device__ __forceinline__ void cpa16(uint32_t s, const void* g) {
    asm volatile("cp.async.cg.shared.global [%0], [%1], 16;" :: "r"(s), "l"(g) : "memory");
}
#define CP_COMMIT() asm volatile("cp.async.commit_group;" ::: "memory")
#define CP_WAIT0()  asm volatile("cp.async.wait_group 0;" ::: "memory")
#define CP_WAIT1()  asm volatile("cp.async.wait_group 1;" ::: "memory")

__device__ __forceinline__ void ldsm4(uint32_t& r0, uint32_t& r1, uint32_t& r2,
                                      uint32_t& r3, uint32_t addr) {
    asm volatile("ldmatrix.sync.aligned.m8n8.x4.shared.b16 {%0,%1,%2,%3}, [%4];"
                 : "=r"(r0), "=r"(r1), "=r"(r2), "=r"(r3) : "r"(addr));
}
__device__ __forceinline__ void ldsm4t(uint32_t& r0, uint32_t& r1, uint32_t& r2,
                                       uint32_t& r3, uint32_t addr) {
    asm volatile("ldmatrix.sync.aligned.m8n8.x4.trans.shared.b16 {%0,%1,%2,%3}, [%4];"
                 : "=r"(r0), "=r"(r1), "=r"(r2), "=r"(r3) : "r"(addr));
}
__device__ __forceinline__ void mma_f16(float* d, const uint32_t* a, const uint32_t* b) {
    asm volatile(
        "mma.sync.aligned.m16n8k16.row.col.f32.f16.f16.f32 "
        "{%0,%1,%2,%3}, {%4,%5,%6,%7}, {%8,%9}, {%0,%1,%2,%3};"
        : "+f"(d[0]), "+f"(d[1]), "+f"(d[2]), "+f"(d[3])
        : "r"(a[0]), "r"(a[1]), "r"(a[2]), "r"(a[3]), "r"(b[0]), "r"(b[1]));
}

// ---------------------------------------------------------------------------
// fp32 -> fp16 conversion, all 5 tensors in one launch
// ---------------------------------------------------------------------------
#define CN0 (M_*E_/4)
#define CN1 (E_*3*E_/4)
#define CN2 (E_*E_/4)
#define CN3 (E_*FF_/4)
#define CN4 (FF_*E_/4)
#define CNT (CN0+CN1+CN2+CN3+CN4)

__global__ void conv_all(
    const float4* __restrict__ x,   const float4* __restrict__ wqkv,
    const float4* __restrict__ wo,  const float4* __restrict__ wf1,
    const float4* __restrict__ wf2,
    __half2* dx, __half2* dqkv, __half2* dwo, __half2* df1, __half2* df2)
{
    int j = blockIdx.x * blockDim.x + threadIdx.x;
    const float4* s; __half2* d;
    if (j < CN0)              { s = x;    d = dx;   }
    else if ((j -= CN0) < CN1){ s = wqkv; d = dqkv; }
    else if ((j -= CN1) < CN2){ s = wo;   d = dwo;  }
    else if ((j -= CN2) < CN3){ s = wf1;  d = df1;  }
    else { j -= CN3;            s = wf2;  d = df2;  }
    float4 v = s[j];
    d[2*j]   = __floats2half2_rn(v.x, v.y);
    d[2*j+1] = __floats2half2_rn(v.z, v.w);
}

// ===========================================================================
// FP16 mma.sync GEMM: C[M,N] = A[M,K] @ B[K,N] + bias (+GELU).
// CTA 128x128 with 128 threads (4 warps, 2x2 grid), warp tile 64x64.
// BK=32, 3-stage cp.async, single sync/iter, 2 CTAs/SM.
// Rationale: 64x64 warp tile doubles fragment reuse -> smem wavefronts per
// MAC drop 1.5x (crossbar was the binding constraint at 43% tensor).
// A stage: 128 rows x 80B stride (10240B). B: 32 rows x 272B stride (8704B).
// ===========================================================================
#define GA_BYTES (128 * 80)          // 10240
#define GB_BYTES (32 * 272)          // 8704
#define GSTG (GA_BYTES + GB_BYTES)   // 18944
#define GEMM_SMEM (3 * GSTG)         // 56832

template<int ACT, int OUTH>
__global__ void __launch_bounds__(128, 2) gemm_h(
    const __half* __restrict__ A, const __half* __restrict__ Bm,
    const float* __restrict__ bias, void* __restrict__ Cv,
    int M, int N, int K)
{
    extern __shared__ char smraw[];
    const uint32_t sbase = smem_u32(smraw);
    const int tid = threadIdx.x, lane = tid & 31, wid = tid >> 5;
    const int wm = wid & 1, wn = wid >> 1;          // 2x2 warp grid, 64x64 tiles
    const int bm = blockIdx.y << 7, bn = blockIdx.x << 7;

    float acc[4][8][4];
    #pragma unroll
    for (int i = 0; i < 4; i++)
        #pragma unroll
        for (int j = 0; j < 8; j++)
            #pragma unroll
            for (int q = 0; q < 4; q++) acc[i][j][q] = 0.f;

    const __half* Abase = A + (size_t)bm * K;
    const __half* Bbase = Bm + bn;

    auto load_stage = [&](int kt, int slot) {
        const uint32_t a0 = sbase + (uint32_t)slot * GSTG;
        const uint32_t b0 = a0 + GA_BYTES;
        #pragma unroll
        for (int i = 0; i < 4; i++) {
            int idx = tid + (i << 7);
            int r = idx >> 2, c = idx & 3;            // 128 rows x 4 chunks
            cpa16(a0 + (uint32_t)(r * 80 + c * 16),
                  Abase + (size_t)r * K + kt * 32 + c * 8);
        }
        #pragma unroll
        for (int i = 0; i < 4; i++) {
            int idx = tid + (i << 7);
            int r = idx >> 4, c = idx & 15;           // 32 rows x 16 chunks
            cpa16(b0 + (uint32_t)(r * 272 + c * 16),
                  Bbase + (size_t)(kt * 32 + r) * N + c * 8);
        }
    };

    const uint32_t a_lane = (uint32_t)((lane & 15) * 80 + (lane >> 4) * 16);
    const int bK = ((lane >> 3) & 1) * 8 + (lane & 7);
    const int bN = ((lane >> 4) & 1) * 8;

    const int T = K >> 5;
    load_stage(0, 0); CP_COMMIT();
    load_stage(1, 1); CP_COMMIT();

    for (int t = 0; t < T; ++t) {
        CP_WAIT1();          // stage t complete; stage t+1 still in flight
        __syncthreads();     // all warps done reading slot (t+2)%3 (iter t-1)
        if (t + 2 < T) load_stage(t + 2, (t + 2) % 3);
        CP_COMMIT();         // unconditional: uniform group counting

        const int slot = t % 3;
        const uint32_t aS = sbase + (uint32_t)slot * GSTG + (uint32_t)(wm * 64 * 80) + a_lane;
        const uint32_t bS = sbase + (uint32_t)slot * GSTG + GA_BYTES;

        #pragma unroll
        for (int kk = 0; kk < 2; kk++) {
            uint32_t af[4][4];
            #pragma unroll
            for (int mt = 0; mt < 4; mt++)
                ldsm4(af[mt][0], af[mt][1], af[mt][2], af[mt][3],
                      aS + (uint32_t)(mt * 16 * 80 + kk * 32));
            uint32_t bf[8][2];
            #pragma unroll
            for (int ntp = 0; ntp < 4; ntp++) {
                uint32_t r0, r1, r2, r3;
                uint32_t baddr = bS + (uint32_t)((kk * 16 + bK) * 272
                                + (wn * 64 + ntp * 16 + bN) * 2);
                ldsm4t(r0, r1, r2, r3, baddr);
                bf[2*ntp][0] = r0; bf[2*ntp][1] = r1;
                bf[2*ntp+1][0] = r2; bf[2*ntp+1][1] = r3;
            }
            #pragma unroll
            for (int mt = 0; mt < 4; mt++)
                #pragma unroll
                for (int nt = 0; nt < 8; nt++)
                    mma_f16(acc[mt][nt], af[mt], bf[nt]);
        }
    }

    // epilogue: bias (+gelu), fp16 or fp32 out
    #pragma unroll
    for (int mt = 0; mt < 4; mt++) {
        #pragma unroll
        for (int half = 0; half < 2; half++) {
            const int r = bm + wm * 64 + mt * 16 + (lane >> 2) + half * 8;
            #pragma unroll
            for (int nt = 0; nt < 8; nt++) {
                const int c = bn + wn * 64 + nt * 8 + (lane & 3) * 2;
                float v0 = acc[mt][nt][half * 2 + 0] + bias[c];
                float v1 = acc[mt][nt][half * 2 + 1] + bias[c + 1];
                if (ACT) { v0 = gelu_f(v0); v1 = gelu_f(v1); }
                if (OUTH) {
                    __half* C = (__half*)Cv;
                    *(__half2*)(C + (size_t)r * N + c) = __floats2half2_rn(v0, v1);
                } else {
                    float* C = (float*)Cv;
                    *(float2*)(C + (size_t)r * N + c) = make_float2(v0, v1);
                }
            }
        }
    }
}

// ===========================================================================
// Flash attention, fp16 mma. CTA: one (b,h), 64 Q rows, 8 warps 2(M)x4(N).
// Q fragments hoisted out of the KV loop (loop-invariant). (unchanged)
// ===========================================================================
#define OFF_Q  0
#define OFF_K  9216
#define OFF_V  (9216 + 18432)
#define OFF_SF (9216 + 18432 + 18432)
#define OFF_PH (OFF_SF + 17408)
#define OFF_RW (OFF_PH + 9216)
#define FLASH_SMEM (OFF_RW + 768)

__global__ void __launch_bounds__(256, 2) flash_h(
    const __half* __restrict__ qkv, __half* __restrict__ attn)
{
    extern __shared__ char smraw[];
    const uint32_t base = smem_u32(smraw);
    const uint32_t QsU = base + OFF_Q, KsU = base + OFF_K, VsU = base + OFF_V;
    __half* Ph  = (__half*)(smraw + OFF_PH);
    float* Sf   = (float*)(smraw + OFF_SF);
    float* mrow = (float*)(smraw + OFF_RW);
    float* lrow = mrow + 64;
    float* arow = lrow + 64;
    const uint32_t PhU = base + OFF_PH;

    const int tid = threadIdx.x, lane = tid & 31, wid = tid >> 5;
    const int wm = wid & 1, wn = wid >> 1;
    const int q0 = blockIdx.x << 6;
    const int b  = blockIdx.y >> 4, h = blockIdx.y & 15;

    const __half* qb = qkv + (size_t)b * S_ * (3 * E_) + h * HD_;
    const __half* kb = qb + E_;
    const __half* vb = qb + 2 * E_;

    #pragma unroll
    for (int i = 0; i < 2; i++) {
        int idx = tid + (i << 8);
        int r = idx >> 3, c = idx & 7;
        cpa16(QsU + (uint32_t)(r * 144 + c * 16), qb + (size_t)(q0 + r) * (3 * E_) + c * 8);
    }
    auto load_kv = [&](int t, int s) {
        #pragma unroll
        for (int i = 0; i < 2; i++) {
            int idx = tid + (i << 8);
            int r = idx >> 3, c = idx & 7;
            size_t go = (size_t)(t * 64 + r) * (3 * E_) + c * 8;
            cpa16(KsU + (uint32_t)(s * 9216 + r * 144 + c * 16), kb + go);
            cpa16(VsU + (uint32_t)(s * 9216 + r * 144 + c * 16), vb + go);
        }
    };
    load_kv(0, 0);
    CP_COMMIT();
    if (tid < 64) { mrow[tid] = -1e30f; lrow[tid] = 0.f; }

    const uint32_t a_lane = (uint32_t)((lane & 15) * 144 + (lane >> 4) * 16);
    const int rh = lane >> 2, c2 = (lane & 3) * 2;
    const int kKey = ((lane >> 4) & 1) * 8 + (lane & 7);
    const int kDb  = ((lane >> 3) & 1) * 16;
    const int vKey = ((lane >> 3) & 1) * 8 + (lane & 7);
    const int vD   = ((lane >> 4) & 1) * 8;

    CP_WAIT0();
    __syncthreads();

    uint32_t qf[4][2][4];
    #pragma unroll
    for (int kk = 0; kk < 4; kk++)
        #pragma unroll
        for (int mt = 0; mt < 2; mt++)
            ldsm4(qf[kk][mt][0], qf[kk][mt][1], qf[kk][mt][2], qf[kk][mt][3],
                  QsU + (uint32_t)((wm * 32 + mt * 16) * 144 + kk * 32) + a_lane);

    float O[2][2][4];
    #pragma unroll
    for (int a = 0; a < 2; a++)
        #pragma unroll
        for (int bb = 0; bb < 2; bb++)
            #pragma unroll
            for (int q = 0; q < 4; q++) O[a][bb][q] = 0.f;

    const int T = S_ / 64;
    for (int t = 0; t < T; ++t) {
        const int s = t & 1;
        if (t + 1 < T) { load_kv(t + 1, s ^ 1); CP_COMMIT(); }

        float sf[2][2][4];
        #pragma unroll
        for (int a = 0; a < 2; a++)
            #pragma unroll
            for (int bb = 0; bb < 2; bb++)
                #pragma unroll
                for (int q = 0; q < 4; q++) sf[a][bb][q] = 0.f;

        #pragma unroll
        for (int kk = 0; kk < 4; kk++) {
            uint32_t r0, r1, r2, r3;
            uint32_t kaddr = KsU + (uint32_t)(s * 9216 + (wn * 16 + kKey) * 144
                             + kk * 32 + kDb);
            ldsm4(r0, r1, r2, r3, kaddr);
            uint32_t bf[2][2] = {{r0, r1}, {r2, r3}};
            #pragma unroll
            for (int mt = 0; mt < 2; mt++)
                #pragma unroll
                for (int nt = 0; nt < 2; nt++)
                    mma_f16(sf[mt][nt], qf[kk][mt], bf[nt]);
        }
        #pragma unroll
        for (int mt = 0; mt < 2; mt++)
            #pragma unroll
            for (int nt = 0; nt < 2; nt++) {
                int row0 = wm * 32 + mt * 16 + rh;
                int col  = wn * 16 + nt * 8 + c2;
                *(float2*)&Sf[row0 * 68 + col] =
                    make_float2(sf[mt][nt][0] * 0.125f, sf[mt][nt][1] * 0.125f);
                *(float2*)&Sf[(row0 + 8) * 68 + col] =
                    make_float2(sf[mt][nt][2] * 0.125f, sf[mt][nt][3] * 0.125f);
            }
        __syncthreads();

        {
            int row = tid >> 2;
            float* sr = Sf + row * 68 + (tid & 3) * 16;
            float4 v0 = *(float4*)(sr),     v1 = *(float4*)(sr + 4),
                   v2 = *(float4*)(sr + 8), v3 = *(float4*)(sr + 12);
            float mx = fmaxf(fmaxf(fmaxf(v0.x, v0.y), fmaxf(v0.z, v0.w)),
                             fmaxf(fmaxf(v1.x, v1.y), fmaxf(v1.z, v1.w)));
            mx = fmaxf(mx, fmaxf(fmaxf(fmaxf(v2.x, v2.y), fmaxf(v2.z, v2.w)),
                                 fmaxf(fmaxf(v3.x, v3.y), fmaxf(v3.z, v3.w))));
            mx = fmaxf(mx, __shfl_xor_sync(0xffffffffu, mx, 1));
            mx = fmaxf(mx, __shfl_xor_sync(0xffffffffu, mx, 2));
            float mo = mrow[row];
            float mn = fmaxf(mo, mx);
            v0.x = __expf(v0.x - mn); v0.y = __expf(v0.y - mn);
            v0.z = __expf(v0.z - mn); v0.w = __expf(v0.w - mn);
            v1.x = __expf(v1.x - mn); v1.y = __expf(v1.y - mn);
            v1.z = __expf(v1.z - mn); v1.w = __expf(v1.w - mn);
            v2.x = __expf(v2.x - mn); v2.y = __expf(v2.y - mn);
            v2.z = __expf(v2.z - mn); v2.w = __expf(v2.w - mn);
            v3.x = __expf(v3.x - mn); v3.y = __expf(v3.y - mn);
            v3.z = __expf(v3.z - mn); v3.w = __expf(v3.w - mn);
            __half2 hp[8];
            hp[0] = __floats2half2_rn(v0.x, v0.y); hp[1] = __floats2half2_rn(v0.z, v0.w);
            hp[2] = __floats2half2_rn(v1.x, v1.y); hp[3] = __floats2half2_rn(v1.z, v1.w);
            hp[4] = __floats2half2_rn(v2.x, v2.y); hp[5] = __floats2half2_rn(v2.z, v2.w);
            hp[6] = __floats2half2_rn(v3.x, v3.y); hp[7] = __floats2half2_rn(v3.z, v3.w);
            uint4* pdst = (uint4*)(Ph + row * 72 + (tid & 3) * 16);
            pdst[0] = *(uint4*)&hp[0];
            pdst[1] = *(uint4*)&hp[4];
            float su = v0.x + v0.y + v0.z + v0.w + v1.x + v1.y + v1.z + v1.w
                     + v2.x + v2.y + v2.z + v2.w + v3.x + v3.y + v3.z + v3.w;
            su += __shfl_xor_sync(0xffffffffu, su, 1);
            su += __shfl_xor_sync(0xffffffffu, su, 2);
            if ((tid & 3) == 0) {
                float al = __expf(mo - mn);
                arow[row] = al;
                lrow[row] = lrow[row] * al + su;
                mrow[row] = mn;
            }
        }
        __syncthreads();

        #pragma unroll
        for (int mt = 0; mt < 2; mt++) {
            float a0 = arow[wm * 32 + mt * 16 + rh];
            float a1 = arow[wm * 32 + mt * 16 + 8 + rh];
            #pragma unroll
            for (int nt = 0; nt < 2; nt++) {
                O[mt][nt][0] *= a0; O[mt][nt][1] *= a0;
                O[mt][nt][2] *= a1; O[mt][nt][3] *= a1;
            }
        }
        #pragma unroll
        for (int kk = 0; kk < 4; kk++) {
            uint32_t af[2][4];
            #pragma unroll
            for (int mt = 0; mt < 2; mt++)
                ldsm4(af[mt][0], af[mt][1], af[mt][2], af[mt][3],
                      PhU + (uint32_t)((wm * 32 + mt * 16) * 144 + kk * 32) + a_lane);
            uint32_t r0, r1, r2, r3;
            uint32_t vaddr = VsU + (uint32_t)(s * 9216 + (kk * 16 + vKey) * 144
                             + (wn * 16 + vD) * 2);
            ldsm4t(r0, r1, r2, r3, vaddr);
            uint32_t bf[2][2] = {{r0, r1}, {r2, r3}};
            #pragma unroll
            for (int mt = 0; mt < 2; mt++)
                #pragma unroll
                for (int nt = 0; nt < 2; nt++)
                    mma_f16(O[mt][nt], af[mt], bf[nt]);
        }

        if (t + 1 < T) CP_WAIT0();
        __syncthreads();
    }

    #pragma unroll
    for (int mt = 0; mt < 2; mt++) {
        int row0 = wm * 32 + mt * 16 + rh;
        float inv0 = 1.f / lrow[row0];
        float inv1 = 1.f / lrow[row0 + 8];
        #pragma unroll
        for (int nt = 0; nt < 2; nt++) {
            int col = h * HD_ + wn * 16 + nt * 8 + c2;
            *(__half2*)&attn[(size_t)(b * S_ + q0 + row0) * E_ + col] =
                __floats2half2_rn(O[mt][nt][0] * inv0, O[mt][nt][1] * inv0);
            *(__half2*)&attn[(size_t)(b * S_ + q0 + row0 + 8) * E_ + col] =
                __floats2half2_rn(O[mt][nt][2] * inv1, O[mt][nt][3] * inv1);
        }
    }
}

// ---------------------------------------------------------------------------
// Fused residual-add + LayerNorm; optional fp16 secondary output.
// ---------------------------------------------------------------------------
template<int WH>
__global__ void __launch_bounds__(256) ln_kernel(
    const float* __restrict__ a, const float* __restrict__ bsrc,
    const float* __restrict__ g, const float* __restrict__ be,
    float* __restrict__ out, __half* __restrict__ outh)
{
    const int tok = blockIdx.x;
    const int tid = threadIdx.x;
    const float* pa = a    + (size_t)tok * E_;
    const float* pb = bsrc + (size_t)tok * E_;

    float r[4]; float s = 0.f;
    #pragma unroll
    for (int i = 0; i < 4; i++) {
        int e = tid + (i << 8);
        r[i] = pa[e] + pb[e];
        s += r[i];
    }
    __shared__ float red[8];
    #pragma unroll
    for (int o = 16; o > 0; o >>= 1) s += __shfl_xor_sync(0xffffffffu, s, o);
    if ((tid & 31) == 0) red[tid >> 5] = s;
    __syncthreads();
    float tot = 0.f;
    #pragma unroll
    for (int w = 0; w < 8; w++) tot += red[w];
    const float mean = tot * (1.0f / E_);

    float vs = 0.f;
    #pragma unroll
    for (int i = 0; i < 4; i++) { float d = r[i] - mean; vs += d * d; }
    #pragma unroll
    for (int o = 16; o > 0; o >>= 1) vs += __shfl_xor_sync(0xffffffffu, vs, o);
    __syncthreads();
    if ((tid & 31) == 0) red[tid >> 5] = vs;
    __syncthreads();
    float vtot = 0.f;
    #pragma unroll
    for (int w = 0; w < 8; w++) vtot += red[w];
    const float rstd = rsqrtf(vtot * (1.0f / E_) + 1e-5f);

    #pragma unroll
    for (int i = 0; i < 4; i++) {
        int e = tid + (i << 8);
        float v = (r[i] - mean) * rstd * g[e] + be[e];
        out[(size_t)tok * E_ + e] = v;
        if (WH) outh[(size_t)tok * E_ + e] = __float2half(v);
    }
}

// ---------------------------------------------------------------------------
extern "C" void kernel_launch(void* const* d_in, const int* in_sizes, int n_in,
                              void* d_out, int out_size)
{
    const float* x     = (const float*)d_in[0];
    const float* w_qkv = (const float*)d_in[1];
    const float* b_qkv = (const float*)d_in[2];
    const float* w_out = (const float*)d_in[3];
    const float* b_out = (const float*)d_in[4];
    const float* w_ff1 = (const float*)d_in[5];
    const float* b_ff1 = (const float*)d_in[6];
    const float* w_ff2 = (const float*)d_in[7];
    const float* b_ff2 = (const float*)d_in[8];
    const float* g1    = (const float*)d_in[9];
    const float* be1   = (const float*)d_in[10];
    const float* g2    = (const float*)d_in[11];
    const float* be2   = (const float*)d_in[12];
    float* out = (float*)d_out;

    __half *p_hx, *p_wqkv, *p_wout, *p_wff1, *p_wff2;
    __half *p_qkv, *p_attn, *p_x1h, *p_ff1;
    float *p_proj, *p_x1f, *p_ff2;
    cudaGetSymbolAddress((void**)&p_hx,   h_x);
    cudaGetSymbolAddress((void**)&p_wqkv, h_wqkv);
    cudaGetSymbolAddress((void**)&p_wout, h_wout);
    cudaGetSymbolAddress((void**)&p_wff1, h_wff1);
    cudaGetSymbolAddress((void**)&p_wff2, h_wff2);
    cudaGetSymbolAddress((void**)&p_qkv,  h_qkv);
    cudaGetSymbolAddress((void**)&p_attn, h_attn);
    cudaGetSymbolAddress((void**)&p_x1h,  h_x1);
    cudaGetSymbolAddress((void**)&p_ff1,  h_ff1);
    cudaGetSymbolAddress((void**)&p_proj, s_proj);
    cudaGetSymbolAddress((void**)&p_x1f,  s_x1f);
    cudaGetSymbolAddress((void**)&p_ff2,  s_ff2);

    cudaFuncSetAttribute(gemm_h<0,1>, cudaFuncAttributeMaxDynamicSharedMemorySize, GEMM_SMEM);
    cudaFuncSetAttribute(gemm_h<0,0>, cudaFuncAttributeMaxDynamicSharedMemorySize, GEMM_SMEM);
    cudaFuncSetAttribute(gemm_h<1,1>, cudaFuncAttributeMaxDynamicSharedMemorySize, GEMM_SMEM);
    cudaFuncSetAttribute(flash_h,     cudaFuncAttributeMaxDynamicSharedMemorySize, FLASH_SMEM);

    // 0) fp32 -> fp16 conversions (single launch)
    conv_all<<<CNT / 256, 256>>>(
        (const float4*)x, (const float4*)w_qkv, (const float4*)w_out,
        (const float4*)w_ff1, (const float4*)w_ff2,
        (__half2*)p_hx, (__half2*)p_wqkv, (__half2*)p_wout,
        (__half2*)p_wff1, (__half2*)p_wff2);

    // 1) QKV projection (fp16 out)
    gemm_h<0,1><<<dim3(3 * E_ / 128, M_ / 128), 128, GEMM_SMEM>>>(
        p_hx, p_wqkv, b_qkv, p_qkv, M_, 3 * E_, E_);

    // 2) flash attention (fp16)
    flash_h<<<dim3(S_ / 64, B_ * H_), 256, FLASH_SMEM>>>(p_qkv, p_attn);

    // 3) output projection (fp32 out)
    gemm_h<0,0><<<dim3(E_ / 128, M_ / 128), 128, GEMM_SMEM>>>(
        p_attn, p_wout, b_out, p_proj, M_, E_, E_);

    // 4) LN1 (fp32 + fp16 out)
    ln_kernel<1><<<M_, 256>>>(x, p_proj, g1, be1, p_x1f, p_x1h);

    // 5) FF1 + GELU (fp16 out)
    gemm_h<1,1><<<dim3(FF_ / 128, M_ / 128), 128, GEMM_SMEM>>>(
        p_x1h, p_wff1, b_ff1, p_ff1, M_, FF_, E_);

    // 6) FF2 (fp32 out)
    gemm_h<0,0><<<dim3(E_ / 128, M_ / 128), 128, GEMM_SMEM>>>(
        p_ff1, p_wff2, b_ff2, p_ff2, M_, E_, FF_);

    // 7) LN2 -> output
    ln_kernel<0><<<M_, 256>>>(p_x1f, p_ff2, g2, be2, out, nullptr);
}